// round 10
// baseline (speedup 1.0000x reference)
#include <cuda_runtime.h>
#include <cuda_fp16.h>
#include <math.h>
#include <stdint.h>

#define B 2
#define T 2048
#define V 32000
#define D 1024
#define DF 4096
#define L 6
#define BT (B*T)

// ---------------- scratch (device globals; no allocation allowed) ----------
__device__ __align__(1024) float  g_x[(size_t)BT * D];
__device__ __align__(1024) __half g_x16[(size_t)BT * D];
__device__ __align__(1024) __half g_qkv16[(size_t)3 * BT * D];
__device__ __align__(1024) __half g_v16T[(size_t)BT * D];
__device__ __align__(1024) float  g_attn[(size_t)BT * D];
__device__ __align__(1024) float  g_scores[(size_t)B * T * T];
__device__ __align__(1024) __half g_probs16[(size_t)B * T * T];
__device__ __align__(1024) __half g_h16[(size_t)BT * DF];
__device__ __align__(1024) __half g_wqkv16[(size_t)L * 3 * D * D];
__device__ __align__(1024) __half g_w1T16[(size_t)L * DF * D];
__device__ __align__(1024) __half g_w2T16[(size_t)L * D * DF];
__device__ __align__(1024) __half g_wout16[(size_t)V * D];

// ---------------- low-level helpers -----------------------------------------
__device__ __forceinline__ uint32_t smem_u32(const void* p) {
    uint32_t a;
    asm("{ .reg .u64 t; cvta.to.shared.u64 t, %1; cvt.u32.u64 %0, t; }" : "=r"(a) : "l"(p));
    return a;
}
__device__ __forceinline__ void cp16(void* smem_dst, const void* gmem_src) {
    uint32_t s = (uint32_t)__cvta_generic_to_shared(smem_dst);
    asm volatile("cp.async.cg.shared.global [%0], [%1], 16;" :: "r"(s), "l"(gmem_src));
}
__device__ __forceinline__ void cp_commit() {
    asm volatile("cp.async.commit_group;" ::: "memory");
}
template<int N>
__device__ __forceinline__ void cp_wait() {
    asm volatile("cp.async.wait_group %0;" :: "n"(N) : "memory");
}
__device__ __forceinline__ void ldsm4(uint32_t addr, uint32_t& r0, uint32_t& r1,
                                      uint32_t& r2, uint32_t& r3) {
    asm volatile("ldmatrix.sync.aligned.m8n8.x4.shared.b16 {%0,%1,%2,%3}, [%4];"
                 : "=r"(r0), "=r"(r1), "=r"(r2), "=r"(r3) : "r"(addr));
}

__device__ __forceinline__ float block_sum(float v, float* red) {
    int tid = threadIdx.x, lane = tid & 31, warp = tid >> 5;
    int nw = blockDim.x >> 5;
    #pragma unroll
    for (int o = 16; o; o >>= 1) v += __shfl_xor_sync(0xffffffffu, v, o);
    if (lane == 0) red[warp] = v;
    __syncthreads();
    float r = (tid < nw) ? red[tid] : 0.0f;
    if (warp == 0) {
        #pragma unroll
        for (int o = 16; o; o >>= 1) r += __shfl_xor_sync(0xffffffffu, r, o);
        if (tid == 0) red[0] = r;
    }
    __syncthreads();
    float out = red[0];
    __syncthreads();
    return out;
}
__device__ __forceinline__ float block_max(float v, float* red) {
    int tid = threadIdx.x, lane = tid & 31, warp = tid >> 5;
    int nw = blockDim.x >> 5;
    #pragma unroll
    for (int o = 16; o; o >>= 1) v = fmaxf(v, __shfl_xor_sync(0xffffffffu, v, o));
    if (lane == 0) red[warp] = v;
    __syncthreads();
    float r = (tid < nw) ? red[tid] : -INFINITY;
    if (warp == 0) {
        #pragma unroll
        for (int o = 16; o; o >>= 1) r = fmaxf(r, __shfl_xor_sync(0xffffffffu, r, o));
        if (tid == 0) red[0] = r;
    }
    __syncthreads();
    float out = red[0];
    __syncthreads();
    return out;
}

// ---------------- embed + positional encoding -------------------------------
__global__ void embed_pe_kernel(const int* __restrict__ tokens,
                                const float* __restrict__ embed,
                                float* __restrict__ x, __half* __restrict__ x16) {
    const int row = blockIdx.x;
    const int t = row % T;
    const int tok = tokens[row];
    const float* erow = embed + (size_t)tok * D;
    float* xrow = x + (size_t)row * D;
    __half* xrow16 = x16 + (size_t)row * D;
    for (int i = threadIdx.x; i < D; i += blockDim.x) {
        int ip = i & ~1;
        double freq = exp(((double)ip / (double)D) * log(10000.0));
        double angle = (double)t / freq;
        float pe = (i & 1) ? (float)cos(angle) : (float)sin(angle);
        float v = erow[i] + pe;
        xrow[i] = v;
        xrow16[i] = __float2half(v);
    }
}

// ---------------- transpose fp32 -> fp16 [R,C] -> [C,R], batched -------------
__global__ void transpose_f2h_kernel(const float* __restrict__ in, __half* __restrict__ out,
                                     int R, int C, long inStride, long outStride) {
    __shared__ float tile[32][33];
    const long zi = blockIdx.z;
    in  += zi * inStride;
    out += zi * outStride;
    const int c0 = blockIdx.x * 32, r0 = blockIdx.y * 32;
    const int tx = threadIdx.x, ty = threadIdx.y;   // 32 x 8
    #pragma unroll
    for (int j = 0; j < 32; j += 8)
        tile[ty + j][tx] = in[(long)(r0 + ty + j) * C + c0 + tx];
    __syncthreads();
    #pragma unroll
    for (int j = 0; j < 32; j += 8)
        out[(long)(c0 + ty + j) * R + r0 + tx] = __float2half(tile[tx][ty + j]);
}

// ---------------- transpose fp16 -> fp16 [R,C] -> [C,R], batched -------------
__global__ void transpose_h2h_kernel(const __half* __restrict__ in, __half* __restrict__ out,
                                     int R, int C, long inStride, long outStride) {
    __shared__ __half tile[32][36];
    const long zi = blockIdx.z;
    in  += zi * inStride;
    out += zi * outStride;
    const int c0 = blockIdx.x * 32, r0 = blockIdx.y * 32;
    const int tx = threadIdx.x, ty = threadIdx.y;   // 32 x 8
    #pragma unroll
    for (int j = 0; j < 32; j += 8)
        tile[ty + j][tx] = in[(long)(r0 + ty + j) * C + c0 + tx];
    __syncthreads();
    #pragma unroll
    for (int j = 0; j < 32; j += 8)
        out[(long)(c0 + ty + j) * R + r0 + tx] = tile[tx][ty + j];
}

// ---------------- FP16 mma.sync TT GEMM --------------------------------------
// C[M,N] = A[M,K] @ Bt[N,K]^T (+bias)(+relu). A,Bt fp16 K-major, fp32 accum.
// 128x128 CTA tile, 4 warps of 64x64 (128 threads), BK=32, 4-stage cp.async.
// CAUSAL: 0 none, 1 skip tiles above diagonal, 2 K truncated at bm+128.
// OUT16: write __half C, else float C.
#define RST 40                                  // halves per smem row (80 B)
#define STAGE_H (256 * RST)                     // halves per stage (A 128 + B 128)
#define NSTAGE 4
#define GEMM_SMEM16 (NSTAGE * STAGE_H * 2)      // 81920 B

template<int CAUSAL, bool RELU, bool BIAS, bool OUT16>
__global__ __launch_bounds__(128, 2) void gemm16(
    const __half* __restrict__ A, const __half* __restrict__ Bt,
    const float* __restrict__ b0, const float* __restrict__ b1, const float* __restrict__ b2,
    void* __restrict__ Cv, int N, int K, long sA, long sB, long sC)
{
    extern __shared__ __half smh[];

    const int bm = blockIdx.y * 128;
    const int bn = blockIdx.x * 128;
    if (CAUSAL == 1 && bn > bm + 127) return;
    const int z = blockIdx.z;
    A  += (long)z * sA;
    Bt += (long)z * sB;

    const int tid = threadIdx.x, warp = tid >> 5, lane = tid & 31;
    const int g = lane >> 2, cg = lane & 3;
    const int wm = (warp >> 1) * 64, wn = (warp & 1) * 64;   // 2x2 warps, 64x64 each

    const int Kend = (CAUSAL == 2) ? min(K, bm + 128) : K;
    const int KT = Kend >> 5;

    const uint32_t sbase = smem_u32(smh);

    // ldmatrix.x4 per-lane byte offsets within a stage (canonical m16n8k16 map)
    uint32_t aoff[4], boff[4];
    #pragma unroll
    for (int mi = 0; mi < 4; mi++)
        aoff[mi] = (uint32_t)((wm + mi * 16 + (lane & 15)) * RST * 2 + (lane >> 4) * 16);
    #pragma unroll
    for (int np = 0; np < 4; np++)
        boff[np] = (uint32_t)((128 + wn + np * 16 + (lane & 15)) * RST * 2 + (lane >> 4) * 16);

    auto issue = [&](int s) {
        if (s >= KT) { cp_commit(); return; }
        const int k0 = s << 5;
        __half* As = smh + (s % NSTAGE) * STAGE_H;
        __half* Bs = As + 128 * RST;
        #pragma unroll
        for (int i = 0; i < 4; i++) {
            int idx = tid + i * 128;
            int r = idx >> 2, c = (idx & 3) * 8;
            cp16(&As[r * RST + c], A + (long)(bm + r) * K + k0 + c);
            cp16(&Bs[r * RST + c], Bt + (long)(bn + r) * K + k0 + c);
        }
        cp_commit();
    };

    float acc[4][8][4];
    #pragma unroll
    for (int mi = 0; mi < 4; mi++)
        #pragma unroll
        for (int ni = 0; ni < 8; ni++)
            #pragma unroll
            for (int j = 0; j < 4; j++) acc[mi][ni][j] = 0.0f;

    auto comp = [&](int slot) {
        const uint32_t st = sbase + (uint32_t)slot * (STAGE_H * 2);
        #pragma unroll
        for (int ks = 0; ks < 2; ks++) {
            uint32_t af[4][4];
            uint32_t bf[8][2];
            #pragma unroll
            for (int mi = 0; mi < 4; mi++)
                ldsm4(st + aoff[mi] + ks * 32, af[mi][0], af[mi][1], af[mi][2], af[mi][3]);
            #pragma unroll
            for (int np = 0; np < 4; np++) {
                uint32_t q0, q1, q2, q3;
                ldsm4(st + boff[np] + ks * 32, q0, q1, q2, q3);
                bf[2 * np][0] = q0; bf[2 * np][1] = q2;
                bf[2 * np + 1][0] = q1; bf[2 * np + 1][1] = q3;
            }
            #pragma unroll
            for (int mi = 0; mi < 4; mi++)
                #pragma unroll
                for (int ni = 0; ni < 8; ni++)
                    asm volatile(
                        "mma.sync.aligned.m16n8k16.row.col.f32.f16.f16.f32 "
                        "{%0,%1,%2,%3}, {%4,%5,%6,%7}, {%8,%9}, {%0,%1,%2,%3};"
                        : "+f"(acc[mi][ni][0]), "+f"(acc[mi][ni][1]),
                          "+f"(acc[mi][ni][2]), "+f"(acc[mi][ni][3])
                        : "r"(af[mi][0]), "r"(af[mi][1]), "r"(af[mi][2]), "r"(af[mi][3]),
                          "r"(bf[ni][0]), "r"(bf[ni][1]));
        }
    };

    issue(0);
    issue(1);
    issue(2);
    for (int i = 0; i < KT; i++) {
        cp_wait<2>();
        __syncthreads();
        issue(i + 3);
        comp(i % NSTAGE);
    }

    // epilogue
    const float* bias = BIAS ? (z == 0 ? b0 : (z == 1 ? b1 : b2)) : b0;
    float*  Cf = (float*)Cv  + (long)z * sC;
    __half* Ch = (__half*)Cv + (long)z * sC;
    #pragma unroll
    for (int mi = 0; mi < 4; mi++) {
        const long r0 = bm + wm + mi * 16 + g;
        #pragma unroll
        for (int ni = 0; ni < 8; ni++) {
            const int col = bn + wn + ni * 8 + cg * 2;
            float bb0 = 0.0f, bb1 = 0.0f;
            if (BIAS) { bb0 = bias[col]; bb1 = bias[col + 1]; }
            float2 v0 = make_float2(acc[mi][ni][0] + bb0, acc[mi][ni][1] + bb1);
            float2 v1 = make_float2(acc[mi][ni][2] + bb0, acc[mi][ni][3] + bb1);
            if (RELU) {
                v0.x = fmaxf(v0.x, 0.0f); v0.y = fmaxf(v0.y, 0.0f);
                v1.x = fmaxf(v1.x, 0.0f); v1.y = fmaxf(v1.y, 0.0f);
            }
            if (OUT16) {
                *(__half2*)(Ch + r0 * N + col)       = __floats2half2_rn(v0.x, v0.y);
                *(__half2*)(Ch + (r0 + 8) * N + col) = __floats2half2_rn(v1.x, v1.y);
            } else {
                *(float2*)(Cf + r0 * N + col)       = v0;
                *(float2*)(Cf + (r0 + 8) * N + col) = v1;
            }
        }
    }
}

// ---------------- causal softmax: fp32 scores -> fp16 probs ------------------
__global__ void softmax_causal_kernel(const float* __restrict__ scores,
                                      __half* __restrict__ probs) {
    const int t = blockIdx.x;
    const int b = blockIdx.y;
    const float* row = scores + ((size_t)b * T + t) * T;
    __half* prow = probs + ((size_t)b * T + t) * T;
    const int n = t + 1;
    const float inv_scale = 0.03125f;   // 1/sqrt(1024)
    __shared__ float red[32];
    const int tid = threadIdx.x;

    float m = -INFINITY;
    for (int s = tid; s < n; s += blockDim.x) m = fmaxf(m, row[s] * inv_scale);
    m = block_max(m, red);

    float sum = 0.0f;
    for (int s = tid; s < n; s += blockDim.x) sum += expf(row[s] * inv_scale - m);
    sum = block_sum(sum, red);
    const float inv = 1.0f / sum;

    for (int s = tid; s < n; s += blockDim.x)
        prow[s] = __float2half(expf(row[s] * inv_scale - m) * inv);
    for (int s = n + tid; s < T; s += blockDim.x) prow[s] = __float2half(0.0f);
}

// ---------------- x = LayerNorm(x + y) * g + beta  (fp32 + fp16 out) ---------
__global__ void add_ln_kernel(float* __restrict__ x, __half* __restrict__ x16,
                              const float* __restrict__ y,
                              const float* __restrict__ g, const float* __restrict__ beta) {
    const int row = blockIdx.x;
    __shared__ float buf[D];
    __shared__ float red[32];
    float* xr = x + (size_t)row * D;
    __half* xr16 = x16 + (size_t)row * D;
    const float* yr = y + (size_t)row * D;
    const int tid = threadIdx.x;

    float sum = 0.0f;
    for (int i = tid; i < D; i += blockDim.x) {
        float v = xr[i] + yr[i];
        buf[i] = v;
        sum += v;
    }
    __syncthreads();
    sum = block_sum(sum, red);
    const float mu = sum * (1.0f / D);

    float vs = 0.0f;
    for (int i = tid; i < D; i += blockDim.x) {
        float d = buf[i] - mu;
        vs += d * d;
    }
    vs = block_sum(vs, red);
    const float rstd = rsqrtf(vs * (1.0f / D) + 1e-5f);

    for (int i = tid; i < D; i += blockDim.x) {
        float o = (buf[i] - mu) * rstd * g[i] + beta[i];
        xr[i] = o;
        xr16[i] = __float2half(o);
    }
}

// ---------------- in-place log_softmax over vocab ----------------------------
__global__ void log_softmax_kernel(float* __restrict__ out) {
    float* row = out + (size_t)blockIdx.x * V;
    __shared__ float red[32];
    const int tid = threadIdx.x;

    float m = -INFINITY, s = 0.0f;
    for (int i = tid; i < V; i += blockDim.x) {
        float v = row[i];
        if (v > m) { s = s * expf(m - v) + 1.0f; m = v; }
        else s += expf(v - m);
    }
    float M = block_max(m, red);
    float sum = block_sum(s * expf(m - M), red);
    const float lse = M + logf(sum);

    for (int i = tid; i < V; i += blockDim.x) row[i] -= lse;
}

// ---------------- launch -------------------------------------------------------
extern "C" void kernel_launch(void* const* d_in, const int* in_sizes, int n_in,
                              void* d_out, int out_size) {
    const int*   tokens = (const int*)  d_in[0];
    const float* embed  = (const float*)d_in[1];
    const float* Wq     = (const float*)d_in[2];
    const float* bq     = (const float*)d_in[3];
    const float* Wk     = (const float*)d_in[4];
    const float* bk     = (const float*)d_in[5];
    const float* Wv     = (const float*)d_in[6];
    const float* bv     = (const float*)d_in[7];
    const float* g1     = (const float*)d_in[8];
    const float* beta1  = (const float*)d_in[9];
    const float* W1     = (const float*)d_in[10];
    const float* bf1    = (const float*)d_in[11];
    const float* W2     = (const float*)d_in[12];
    const float* bf2    = (const float*)d_in[13];
    const float* g2     = (const float*)d_in[14];
    const float* beta2  = (const float*)d_in[15];
    const float* Wout   = (const float*)d_in[16];
    const float* bout   = (const float*)d_in[17];
    float* out = (float*)d_out;

    float *x, *attn, *scores;
    __half *x16, *qkv16, *v16T, *probs16, *h16, *wqkv16, *w1T16, *w2T16, *wout16;
    cudaGetSymbolAddress((void**)&x,       g_x);
    cudaGetSymbolAddress((void**)&x16,     g_x16);
    cudaGetSymbolAddress((void**)&qkv16,   g_qkv16);
    cudaGetSymbolAddress((void**)&v16T,    g_v16T);
    cudaGetSymbolAddress((void**)&attn,    g_attn);
    cudaGetSymbolAddress((void**)&scores,  g_scores);
    cudaGetSymbolAddress((void**)&probs16, g_probs16);
    cudaGetSymbolAddress((void**)&h16,     g_h16);
    cudaGetSymbolAddress((void**)&wqkv16,  g_wqkv16);
    cudaGetSymbolAddress((void**)&w1T16,   g_w1T16);
    cudaGetSymbolAddress((void**)&w2T16,   g_w2T16);
    cudaGetSymbolAddress((void**)&wout16,  g_wout16);
    __half* q16 = qkv16;
    __half* k16 = qkv16 + (size_t)BT * D;
    __half* v16 = qkv16 + (size_t)2 * BT * D;

    cudaFuncSetAttribute(gemm16<0, false, true,  true>,  cudaFuncAttributeMaxDynamicSharedMemorySize, GEMM_SMEM16);
    cudaFuncSetAttribute(gemm16<0, true,  true,  true>,  cudaFuncAttributeMaxDynamicSharedMemorySize, GEMM_SMEM16);
    cudaFuncSetAttribute(gemm16<0, false, true,  false>, cudaFuncAttributeMaxDynamicSharedMemorySize, GEMM_SMEM16);
    cudaFuncSetAttribute(gemm16<1, false, false, false>, cudaFuncAttributeMaxDynamicSharedMemorySize, GEMM_SMEM16);
    cudaFuncSetAttribute(gemm16<2, false, false, false>, cudaFuncAttributeMaxDynamicSharedMemorySize, GEMM_SMEM16);

    // ---- weight transposes to [N,K] K-major fp16 ----
    dim3 tb(32, 8);
    transpose_f2h_kernel<<<dim3(D / 32, D / 32, L), tb>>>(Wq, wqkv16 + 0 * (size_t)D * D, D, D, (long)D * D, (long)3 * D * D);
    transpose_f2h_kernel<<<dim3(D / 32, D / 32, L), tb>>>(Wk, wqkv16 + 1 * (size_t)D * D, D, D, (long)D * D, (long)3 * D * D);
    transpose_f2h_kernel<<<dim3(D / 32, D / 32, L), tb>>>(Wv, wqkv16 + 2 * (size_t)D * D, D, D, (long)D * D, (long)3 * D * D);
    transpose_f2h_kernel<<<dim3(DF / 32, D / 32, L), tb>>>(W1, w1T16, D, DF, (long)D * DF, (long)DF * D);
    transpose_f2h_kernel<<<dim3(D / 32, DF / 32, L), tb>>>(W2, w2T16, DF, D, (long)DF * D, (long)D * DF);
    transpose_f2h_kernel<<<dim3(V / 32, D / 32, 1), tb>>>(Wout, wout16, D, V, 0, 0);

    embed_pe_kernel<<<BT, 256>>>(tokens, embed, x, x16);

    for (int l = 0; l < L; ++l) {
        // fused QKV -> fp16 (z = 0,1,2 selects weight slice + bias + out slice)
        gemm16<0, false, true, true><<<dim3(D / 128, BT / 128, 3), 128, GEMM_SMEM16>>>(
            x16, wqkv16 + (size_t)l * 3 * D * D,
            bq + (size_t)l * D, bk + (size_t)l * D, bv + (size_t)l * D,
            qkv16, D, D, 0, (long)D * D, (long)BT * D);

        // scores = q @ k^T per batch -> fp32 (causal tile skip)
        gemm16<1, false, false, false><<<dim3(T / 128, T / 128, B), 128, GEMM_SMEM16>>>(
            q16, k16, nullptr, nullptr, nullptr,
            scores, T, D, (long)T * D, (long)T * D, (long)T * T);

        softmax_causal_kernel<<<dim3(T, B, 1), 256>>>(scores, probs16);

        // v^T per batch: [T,D] -> [D,T] (fp16)
        transpose_h2h_kernel<<<dim3(D / 32, T / 32, B), tb>>>(v16, v16T, T, D, (long)T * D, (long)D * T);

        // attn = probs @ v -> fp32 (K truncated at bm+128)
        gemm16<2, false, false, false><<<dim3(D / 128, T / 128, B), 128, GEMM_SMEM16>>>(
            probs16, v16T, nullptr, nullptr, nullptr,
            attn, D, T, (long)T * T, (long)D * T, (long)T * D);

        add_ln_kernel<<<BT, 256>>>(x, x16, attn, g1 + (size_t)l * D, beta1 + (size_t)l * D);

        // FFN1 -> fp16 h (relu)
        gemm16<0, true, true, true><<<dim3(DF / 128, BT / 128, 1), 128, GEMM_SMEM16>>>(
            x16, w1T16 + (size_t)l * DF * D,
            bf1 + (size_t)l * DF, nullptr, nullptr,
            h16, DF, D, 0, 0, 0);
        // FFN2 -> fp32 attn
        gemm16<0, false, true, false><<<dim3(D / 128, BT / 128, 1), 128, GEMM_SMEM16>>>(
            h16, w2T16 + (size_t)l * D * DF,
            bf2 + (size_t)l * D, nullptr, nullptr,
            attn, D, DF, 0, 0, 0);

        add_ln_kernel<<<BT, 256>>>(x, x16, attn, g2 + (size_t)l * D, beta2 + (size_t)l * D);
    }

    // vocab projection -> fp32 out
    gemm16<0, false, true, false><<<dim3(V / 128, BT / 128, 1), 128, GEMM_SMEM16>>>(
        x16, wout16, bout, nullptr, nullptr,
        out, V, D, 0, 0, 0);
    log_softmax_kernel<<<BT, 256>>>(out);
}

// round 11
// speedup vs baseline: 1.0649x; 1.0649x over previous
#include <cuda_runtime.h>
#include <cuda_fp16.h>
#include <math.h>
#include <stdint.h>

#define B 2
#define T 2048
#define V 32000
#define D 1024
#define DF 4096
#define L 6
#define BT (B*T)

// ---------------- scratch (device globals; no allocation allowed) ----------
__device__ __align__(1024) float  g_x[(size_t)BT * D];
__device__ __align__(1024) __half g_x16[(size_t)BT * D];
__device__ __align__(1024) __half g_qkv16[(size_t)3 * BT * D];
__device__ __align__(1024) float  g_attn[(size_t)BT * D];
__device__ __align__(1024) float  g_scores[(size_t)B * T * T];
__device__ __align__(1024) __half g_probs16[(size_t)B * T * T];
__device__ __align__(1024) __half g_h16[(size_t)BT * DF];
__device__ __align__(1024) __half g_wqkv16[(size_t)L * 3 * D * D];
__device__ __align__(1024) __half g_w1T16[(size_t)L * DF * D];
__device__ __align__(1024) __half g_w2T16[(size_t)L * D * DF];
__device__ __align__(1024) __half g_wout16[(size_t)V * D];

// ---------------- low-level helpers -----------------------------------------
__device__ __forceinline__ uint32_t smem_u32(const void* p) {
    uint32_t a;
    asm("{ .reg .u64 t; cvta.to.shared.u64 t, %1; cvt.u32.u64 %0, t; }" : "=r"(a) : "l"(p));
    return a;
}
__device__ __forceinline__ void cp16(void* smem_dst, const void* gmem_src) {
    uint32_t s = (uint32_t)__cvta_generic_to_shared(smem_dst);
    asm volatile("cp.async.cg.shared.global [%0], [%1], 16;" :: "r"(s), "l"(gmem_src));
}
__device__ __forceinline__ void cp_commit() {
    asm volatile("cp.async.commit_group;" ::: "memory");
}
template<int N>
__device__ __forceinline__ void cp_wait() {
    asm volatile("cp.async.wait_group %0;" :: "n"(N) : "memory");
}
__device__ __forceinline__ void ldsm4(uint32_t addr, uint32_t& r0, uint32_t& r1,
                                      uint32_t& r2, uint32_t& r3) {
    asm volatile("ldmatrix.sync.aligned.m8n8.x4.shared.b16 {%0,%1,%2,%3}, [%4];"
                 : "=r"(r0), "=r"(r1), "=r"(r2), "=r"(r3) : "r"(addr));
}
__device__ __forceinline__ void ldsm4t(uint32_t addr, uint32_t& r0, uint32_t& r1,
                                       uint32_t& r2, uint32_t& r3) {
    asm volatile("ldmatrix.sync.aligned.m8n8.x4.trans.shared.b16 {%0,%1,%2,%3}, [%4];"
                 : "=r"(r0), "=r"(r1), "=r"(r2), "=r"(r3) : "r"(addr));
}

__device__ __forceinline__ float block_sum(float v, float* red) {
    int tid = threadIdx.x, lane = tid & 31, warp = tid >> 5;
    int nw = blockDim.x >> 5;
    #pragma unroll
    for (int o = 16; o; o >>= 1) v += __shfl_xor_sync(0xffffffffu, v, o);
    if (lane == 0) red[warp] = v;
    __syncthreads();
    float r = (tid < nw) ? red[tid] : 0.0f;
    if (warp == 0) {
        #pragma unroll
        for (int o = 16; o; o >>= 1) r += __shfl_xor_sync(0xffffffffu, r, o);
        if (tid == 0) red[0] = r;
    }
    __syncthreads();
    float out = red[0];
    __syncthreads();
    return out;
}
__device__ __forceinline__ float block_max(float v, float* red) {
    int tid = threadIdx.x, lane = tid & 31, warp = tid >> 5;
    int nw = blockDim.x >> 5;
    #pragma unroll
    for (int o = 16; o; o >>= 1) v = fmaxf(v, __shfl_xor_sync(0xffffffffu, v, o));
    if (lane == 0) red[warp] = v;
    __syncthreads();
    float r = (tid < nw) ? red[tid] : -INFINITY;
    if (warp == 0) {
        #pragma unroll
        for (int o = 16; o; o >>= 1) r = fmaxf(r, __shfl_xor_sync(0xffffffffu, r, o));
        if (tid == 0) red[0] = r;
    }
    __syncthreads();
    float out = red[0];
    __syncthreads();
    return out;
}

// ---------------- embed + positional encoding -------------------------------
__global__ void embed_pe_kernel(const int* __restrict__ tokens,
                                const float* __restrict__ embed,
                                float* __restrict__ x, __half* __restrict__ x16) {
    const int row = blockIdx.x;
    const int t = row % T;
    const int tok = tokens[row];
    const float* erow = embed + (size_t)tok * D;
    float* xrow = x + (size_t)row * D;
    __half* xrow16 = x16 + (size_t)row * D;
    for (int i = threadIdx.x; i < D; i += blockDim.x) {
        int ip = i & ~1;
        double freq = exp(((double)ip / (double)D) * log(10000.0));
        double angle = (double)t / freq;
        float pe = (i & 1) ? (float)cos(angle) : (float)sin(angle);
        float v = erow[i] + pe;
        xrow[i] = v;
        xrow16[i] = __float2half(v);
    }
}

// ---------------- transpose fp32 -> fp16 [R,C] -> [C,R], batched -------------
__global__ void transpose_f2h_kernel(const float* __restrict__ in, __half* __restrict__ out,
                                     int R, int C, long inStride, long outStride) {
    __shared__ float tile[32][33];
    const long zi = blockIdx.z;
    in  += zi * inStride;
    out += zi * outStride;
    const int c0 = blockIdx.x * 32, r0 = blockIdx.y * 32;
    const int tx = threadIdx.x, ty = threadIdx.y;   // 32 x 8
    #pragma unroll
    for (int j = 0; j < 32; j += 8)
        tile[ty + j][tx] = in[(long)(r0 + ty + j) * C + c0 + tx];
    __syncthreads();
    #pragma unroll
    for (int j = 0; j < 32; j += 8)
        out[(long)(c0 + ty + j) * R + r0 + tx] = __float2half(tile[tx][ty + j]);
}

// ---------------- FP16 mma.sync GEMM -----------------------------------------
// C[M,N] = A[M,K] @ B (+bias)(+relu). A fp16 K-major [M,K].
// TRB=0: B = Bt [N,K] K-major (TT).  TRB=1: B = [K,N] row-major (NN, trans ldmatrix).
// 128x128 CTA tile, 8 warps of 32x64, BK=32 (2x k16), 4-stage cp.async.
// CAUSAL: 0 none, 1 skip tiles above diagonal, 2 K truncated at bm+128.
// OUT16: write __half C, else float C.
#define RST 40                                   // A rows (and TT B rows): 80 B
#define RSTB 136                                 // NN B rows: 272 B
#define STAGE_H (256 * RST)                      // max stage size (TT layout is larger user)
#define NSTAGE 4
#define GEMM_SMEM16 (NSTAGE * STAGE_H * 2)       // 81920 B

template<int CAUSAL, bool RELU, bool BIAS, bool OUT16, int TRB>
__global__ __launch_bounds__(256, 2) void gemm16(
    const __half* __restrict__ A, const __half* __restrict__ Bm,
    const float* __restrict__ b0, const float* __restrict__ b1, const float* __restrict__ b2,
    void* __restrict__ Cv, int N, int K, long sA, long sB, long sC)
{
    extern __shared__ __half smh[];

    const int bm = blockIdx.y * 128;
    const int bn = blockIdx.x * 128;
    if (CAUSAL == 1 && bn > bm + 127) return;
    const int z = blockIdx.z;
    A  += (long)z * sA;
    Bm += (long)z * sB;

    const int tid = threadIdx.x, warp = tid >> 5, lane = tid & 31;
    const int g = lane >> 2, cg = lane & 3;
    const int wm = (warp >> 1) * 32, wn = (warp & 1) * 64;

    const int Kend = (CAUSAL == 2) ? min(K, bm + 128) : K;
    const int KT = Kend >> 5;

    const uint32_t sbase = smem_u32(smh);

    // per-lane ldmatrix byte offsets within a stage
    uint32_t aoff[2], boff[4];
    #pragma unroll
    for (int mi = 0; mi < 2; mi++)
        aoff[mi] = (uint32_t)((wm + mi * 16 + (lane & 15)) * RST * 2 + (lane >> 4) * 16);
    #pragma unroll
    for (int np = 0; np < 4; np++) {
        if (TRB == 0)
            boff[np] = (uint32_t)((128 + wn + np * 16 + (lane & 15)) * RST * 2 + (lane >> 4) * 16);
        else
            boff[np] = (uint32_t)(128 * RST * 2 + (lane & 15) * RSTB * 2
                                  + (wn + np * 16 + (lane >> 4) * 8) * 2);
    }
    constexpr uint32_t BKSTEP = (TRB == 0) ? 32u : (16u * RSTB * 2u);

    auto issue = [&](int s) {
        if (s >= KT) { cp_commit(); return; }
        const int k0 = s << 5;
        __half* As = smh + (s % NSTAGE) * STAGE_H;
        __half* Bs = As + 128 * RST;
        #pragma unroll
        for (int i = 0; i < 2; i++) {
            int idx = tid + i * 256;
            int r = idx >> 2, c = (idx & 3) * 8;
            cp16(&As[r * RST + c], A + (long)(bm + r) * K + k0 + c);
            if (TRB == 0) {
                cp16(&Bs[r * RST + c], Bm + (long)(bn + r) * K + k0 + c);
            } else {
                int rb = idx >> 4, cb = (idx & 15) * 8;   // 32 rows x 128 cols
                cp16(&Bs[rb * RSTB + cb], Bm + (long)(k0 + rb) * N + bn + cb);
            }
        }
        cp_commit();
    };

    float acc[2][8][4];
    #pragma unroll
    for (int mi = 0; mi < 2; mi++)
        #pragma unroll
        for (int ni = 0; ni < 8; ni++)
            #pragma unroll
            for (int j = 0; j < 4; j++) acc[mi][ni][j] = 0.0f;

    auto comp = [&](int slot) {
        const uint32_t st = sbase + (uint32_t)slot * (STAGE_H * 2);
        #pragma unroll
        for (int ks = 0; ks < 2; ks++) {
            uint32_t af[2][4];
            uint32_t bf[8][2];
            #pragma unroll
            for (int mi = 0; mi < 2; mi++)
                ldsm4(st + aoff[mi] + ks * 32, af[mi][0], af[mi][1], af[mi][2], af[mi][3]);
            #pragma unroll
            for (int np = 0; np < 4; np++) {
                uint32_t q0, q1, q2, q3;
                if (TRB == 0) {
                    ldsm4(st + boff[np] + ks * BKSTEP, q0, q1, q2, q3);
                    bf[2 * np][0] = q0; bf[2 * np][1] = q2;
                    bf[2 * np + 1][0] = q1; bf[2 * np + 1][1] = q3;
                } else {
                    ldsm4t(st + boff[np] + ks * BKSTEP, q0, q1, q2, q3);
                    bf[2 * np][0] = q0; bf[2 * np][1] = q1;
                    bf[2 * np + 1][0] = q2; bf[2 * np + 1][1] = q3;
                }
            }
            #pragma unroll
            for (int mi = 0; mi < 2; mi++)
                #pragma unroll
                for (int ni = 0; ni < 8; ni++)
                    asm volatile(
                        "mma.sync.aligned.m16n8k16.row.col.f32.f16.f16.f32 "
                        "{%0,%1,%2,%3}, {%4,%5,%6,%7}, {%8,%9}, {%0,%1,%2,%3};"
                        : "+f"(acc[mi][ni][0]), "+f"(acc[mi][ni][1]),
                          "+f"(acc[mi][ni][2]), "+f"(acc[mi][ni][3])
                        : "r"(af[mi][0]), "r"(af[mi][1]), "r"(af[mi][2]), "r"(af[mi][3]),
                          "r"(bf[ni][0]), "r"(bf[ni][1]));
        }
    };

    issue(0);
    issue(1);
    issue(2);
    for (int i = 0; i < KT; i++) {
        cp_wait<2>();
        __syncthreads();
        issue(i + 3);
        comp(i % NSTAGE);
    }

    // epilogue
    const float* bias = BIAS ? (z == 0 ? b0 : (z == 1 ? b1 : b2)) : b0;
    float*  Cf = (float*)Cv  + (long)z * sC;
    __half* Ch = (__half*)Cv + (long)z * sC;
    #pragma unroll
    for (int mi = 0; mi < 2; mi++) {
        const long r0 = bm + wm + mi * 16 + g;
        #pragma unroll
        for (int ni = 0; ni < 8; ni++) {
            const int col = bn + wn + ni * 8 + cg * 2;
            float bb0 = 0.0f, bb1 = 0.0f;
            if (BIAS) { bb0 = bias[col]; bb1 = bias[col + 1]; }
            float2 v0 = make_float2(acc[mi][ni][0] + bb0, acc[mi][ni][1] + bb1);
            float2 v1 = make_float2(acc[mi][ni][2] + bb0, acc[mi][ni][3] + bb1);
            if (RELU) {
                v0.x = fmaxf(v0.x, 0.0f); v0.y = fmaxf(v0.y, 0.0f);
                v1.x = fmaxf(v1.x, 0.0f); v1.y = fmaxf(v1.y, 0.0f);
            }
            if (OUT16) {
                *(__half2*)(Ch + r0 * N + col)       = __floats2half2_rn(v0.x, v0.y);
                *(__half2*)(Ch + (r0 + 8) * N + col) = __floats2half2_rn(v1.x, v1.y);
            } else {
                *(float2*)(Cf + r0 * N + col)       = v0;
                *(float2*)(Cf + (r0 + 8) * N + col) = v1;
            }
        }
    }
}

// ---------------- causal softmax: fp32 scores -> fp16 probs ------------------
// zero-fill only up to the 128-aligned tile end (attnV truncates K there)
__global__ void softmax_causal_kernel(const float* __restrict__ scores,
                                      __half* __restrict__ probs) {
    const int t = blockIdx.x;
    const int b = blockIdx.y;
    const float* row = scores + ((size_t)b * T + t) * T;
    __half* prow = probs + ((size_t)b * T + t) * T;
    const int n = t + 1;
    const int zend = ((t >> 7) + 1) << 7;   // tile end = bm + 128
    const float inv_scale = 0.03125f;       // 1/sqrt(1024)
    __shared__ float red[32];
    const int tid = threadIdx.x;

    float m = -INFINITY;
    for (int s = tid; s < n; s += blockDim.x) m = fmaxf(m, row[s] * inv_scale);
    m = block_max(m, red);

    float sum = 0.0f;
    for (int s = tid; s < n; s += blockDim.x) sum += expf(row[s] * inv_scale - m);
    sum = block_sum(sum, red);
    const float inv = 1.0f / sum;

    for (int s = tid; s < n; s += blockDim.x)
        prow[s] = __float2half(expf(row[s] * inv_scale - m) * inv);
    for (int s = n + tid; s < zend; s += blockDim.x) prow[s] = __float2half(0.0f);
}

// ---------------- x = LayerNorm(x + y) * g + beta  (fp32 + fp16 out) ---------
__global__ void add_ln_kernel(float* __restrict__ x, __half* __restrict__ x16,
                              const float* __restrict__ y,
                              const float* __restrict__ g, const float* __restrict__ beta) {
    const int row = blockIdx.x;
    __shared__ float buf[D];
    __shared__ float red[32];
    float* xr = x + (size_t)row * D;
    __half* xr16 = x16 + (size_t)row * D;
    const float* yr = y + (size_t)row * D;
    const int tid = threadIdx.x;

    float sum = 0.0f;
    for (int i = tid; i < D; i += blockDim.x) {
        float v = xr[i] + yr[i];
        buf[i] = v;
        sum += v;
    }
    __syncthreads();
    sum = block_sum(sum, red);
    const float mu = sum * (1.0f / D);

    float vs = 0.0f;
    for (int i = tid; i < D; i += blockDim.x) {
        float d = buf[i] - mu;
        vs += d * d;
    }
    vs = block_sum(vs, red);
    const float rstd = rsqrtf(vs * (1.0f / D) + 1e-5f);

    for (int i = tid; i < D; i += blockDim.x) {
        float o = (buf[i] - mu) * rstd * g[i] + beta[i];
        xr[i] = o;
        xr16[i] = __float2half(o);
    }
}

// ---------------- in-place log_softmax over vocab ----------------------------
__global__ void log_softmax_kernel(float* __restrict__ out) {
    float* row = out + (size_t)blockIdx.x * V;
    __shared__ float red[32];
    const int tid = threadIdx.x;

    float m = -INFINITY, s = 0.0f;
    for (int i = tid; i < V; i += blockDim.x) {
        float v = row[i];
        if (v > m) { s = s * expf(m - v) + 1.0f; m = v; }
        else s += expf(v - m);
    }
    float M = block_max(m, red);
    float sum = block_sum(s * expf(m - M), red);
    const float lse = M + logf(sum);

    for (int i = tid; i < V; i += blockDim.x) row[i] -= lse;
}

// ---------------- launch -------------------------------------------------------
extern "C" void kernel_launch(void* const* d_in, const int* in_sizes, int n_in,
                              void* d_out, int out_size) {
    const int*   tokens = (const int*)  d_in[0];
    const float* embed  = (const float*)d_in[1];
    const float* Wq     = (const float*)d_in[2];
    const float* bq     = (const float*)d_in[3];
    const float* Wk     = (const float*)d_in[4];
    const float* bk     = (const float*)d_in[5];
    const float* Wv     = (const float*)d_in[6];
    const float* bv     = (const float*)d_in[7];
    const float* g1     = (const float*)d_in[8];
    const float* beta1  = (const float*)d_in[9];
    const float* W1     = (const float*)d_in[10];
    const float* bf1    = (const float*)d_in[11];
    const float* W2     = (const float*)d_in[12];
    const float* bf2    = (const float*)d_in[13];
    const float* g2     = (const float*)d_in[14];
    const float* beta2  = (const float*)d_in[15];
    const float* Wout   = (const float*)d_in[16];
    const float* bout   = (const float*)d_in[17];
    float* out = (float*)d_out;

    float *x, *attn, *scores;
    __half *x16, *qkv16, *probs16, *h16, *wqkv16, *w1T16, *w2T16, *wout16;
    cudaGetSymbolAddress((void**)&x,       g_x);
    cudaGetSymbolAddress((void**)&x16,     g_x16);
    cudaGetSymbolAddress((void**)&qkv16,   g_qkv16);
    cudaGetSymbolAddress((void**)&attn,    g_attn);
    cudaGetSymbolAddress((void**)&scores,  g_scores);
    cudaGetSymbolAddress((void**)&probs16, g_probs16);
    cudaGetSymbolAddress((void**)&h16,     g_h16);
    cudaGetSymbolAddress((void**)&wqkv16,  g_wqkv16);
    cudaGetSymbolAddress((void**)&w1T16,   g_w1T16);
    cudaGetSymbolAddress((void**)&w2T16,   g_w2T16);
    cudaGetSymbolAddress((void**)&wout16,  g_wout16);
    __half* q16 = qkv16;
    __half* k16 = qkv16 + (size_t)BT * D;
    __half* v16 = qkv16 + (size_t)2 * BT * D;

    cudaFuncSetAttribute(gemm16<0, false, true,  true,  0>, cudaFuncAttributeMaxDynamicSharedMemorySize, GEMM_SMEM16);
    cudaFuncSetAttribute(gemm16<0, true,  true,  true,  0>, cudaFuncAttributeMaxDynamicSharedMemorySize, GEMM_SMEM16);
    cudaFuncSetAttribute(gemm16<0, false, true,  false, 0>, cudaFuncAttributeMaxDynamicSharedMemorySize, GEMM_SMEM16);
    cudaFuncSetAttribute(gemm16<1, false, false, false, 0>, cudaFuncAttributeMaxDynamicSharedMemorySize, GEMM_SMEM16);
    cudaFuncSetAttribute(gemm16<2, false, false, false, 1>, cudaFuncAttributeMaxDynamicSharedMemorySize, GEMM_SMEM16);

    // ---- weight transposes to [N,K] K-major fp16 ----
    dim3 tb(32, 8);
    transpose_f2h_kernel<<<dim3(D / 32, D / 32, L), tb>>>(Wq, wqkv16 + 0 * (size_t)D * D, D, D, (long)D * D, (long)3 * D * D);
    transpose_f2h_kernel<<<dim3(D / 32, D / 32, L), tb>>>(Wk, wqkv16 + 1 * (size_t)D * D, D, D, (long)D * D, (long)3 * D * D);
    transpose_f2h_kernel<<<dim3(D / 32, D / 32, L), tb>>>(Wv, wqkv16 + 2 * (size_t)D * D, D, D, (long)D * D, (long)3 * D * D);
    transpose_f2h_kernel<<<dim3(DF / 32, D / 32, L), tb>>>(W1, w1T16, D, DF, (long)D * DF, (long)DF * D);
    transpose_f2h_kernel<<<dim3(D / 32, DF / 32, L), tb>>>(W2, w2T16, DF, D, (long)DF * D, (long)D * DF);
    transpose_f2h_kernel<<<dim3(V / 32, D / 32, 1), tb>>>(Wout, wout16, D, V, 0, 0);

    embed_pe_kernel<<<BT, 256>>>(tokens, embed, x, x16);

    for (int l = 0; l < L; ++l) {
        // fused QKV -> fp16 (z = 0,1,2 selects weight slice + bias + out slice)
        gemm16<0, false, true, true, 0><<<dim3(D / 128, BT / 128, 3), 256, GEMM_SMEM16>>>(
            x16, wqkv16 + (size_t)l * 3 * D * D,
            bq + (size_t)l * D, bk + (size_t)l * D, bv + (size_t)l * D,
            qkv16, D, D, 0, (long)D * D, (long)BT * D);

        // scores = q @ k^T per batch -> fp32 (causal tile skip)
        gemm16<1, false, false, false, 0><<<dim3(T / 128, T / 128, B), 256, GEMM_SMEM16>>>(
            q16, k16, nullptr, nullptr, nullptr,
            scores, T, D, (long)T * D, (long)T * D, (long)T * T);

        softmax_causal_kernel<<<dim3(T, B, 1), 256>>>(scores, probs16);

        // attn = probs @ V -> fp32 (NN-B via trans ldmatrix; K truncated at bm+128)
        gemm16<2, false, false, false, 1><<<dim3(D / 128, T / 128, B), 256, GEMM_SMEM16>>>(
            probs16, v16, nullptr, nullptr, nullptr,
            attn, D, T, (long)T * T, (long)T * D, (long)T * D);

        add_ln_kernel<<<BT, 256>>>(x, x16, attn, g1 + (size_t)l * D, beta1 + (size_t)l * D);

        // FFN1 -> fp16 h (relu)
        gemm16<0, true, true, true, 0><<<dim3(DF / 128, BT / 128, 1), 256, GEMM_SMEM16>>>(
            x16, w1T16 + (size_t)l * DF * D,
            bf1 + (size_t)l * DF, nullptr, nullptr,
            h16, DF, D, 0, 0, 0);
        // FFN2 -> fp32 attn
        gemm16<0, false, true, false, 0><<<dim3(D / 128, BT / 128, 1), 256, GEMM_SMEM16>>>(
            h16, w2T16 + (size_t)l * D * DF,
            bf2 + (size_t)l * D, nullptr, nullptr,
            attn, D, DF, 0, 0, 0);

        add_ln_kernel<<<BT, 256>>>(x, x16, attn, g2 + (size_t)l * D, beta2 + (size_t)l * D);
    }

    // vocab projection -> fp32 out
    gemm16<0, false, true, false, 0><<<dim3(V / 128, BT / 128, 1), 256, GEMM_SMEM16>>>(
        x16, wout16, bout, nullptr, nullptr,
        out, V, D, 0, 0, 0);
    log_softmax_kernel<<<BT, 256>>>(out);
}

// round 12
// speedup vs baseline: 1.1341x; 1.0650x over previous
#include <cuda_runtime.h>
#include <cuda_fp16.h>
#include <math.h>
#include <stdint.h>

#define B 2
#define T 2048
#define V 32000
#define D 1024
#define DF 4096
#define L 6
#define BT (B*T)

// ---------------- scratch (device globals; no allocation allowed) ----------
__device__ __align__(1024) float  g_x[(size_t)BT * D];
__device__ __align__(1024) __half g_x16[(size_t)BT * D];
__device__ __align__(1024) __half g_qkv16[(size_t)3 * BT * D];
__device__ __align__(1024) float  g_attn[(size_t)BT * D];
__device__ __align__(1024) __half g_scores16[(size_t)B * T * T];
__device__ __align__(1024) __half g_probs16[(size_t)B * T * T];
__device__ __align__(1024) __half g_h16[(size_t)BT * DF];
__device__ __align__(1024) __half g_wqkv16[(size_t)L * 3 * D * D];
__device__ __align__(1024) __half g_w1T16[(size_t)L * DF * D];
__device__ __align__(1024) __half g_w2T16[(size_t)L * D * DF];
__device__ __align__(1024) __half g_wout16[(size_t)V * D];

// ---------------- low-level helpers -----------------------------------------
__device__ __forceinline__ uint32_t smem_u32(const void* p) {
    uint32_t a;
    asm("{ .reg .u64 t; cvta.to.shared.u64 t, %1; cvt.u32.u64 %0, t; }" : "=r"(a) : "l"(p));
    return a;
}
__device__ __forceinline__ void cp16(void* smem_dst, const void* gmem_src) {
    uint32_t s = (uint32_t)__cvta_generic_to_shared(smem_dst);
    asm volatile("cp.async.cg.shared.global [%0], [%1], 16;" :: "r"(s), "l"(gmem_src));
}
__device__ __forceinline__ void cp_commit() {
    asm volatile("cp.async.commit_group;" ::: "memory");
}
template<int N>
__device__ __forceinline__ void cp_wait() {
    asm volatile("cp.async.wait_group %0;" :: "n"(N) : "memory");
}
__device__ __forceinline__ void ldsm4(uint32_t addr, uint32_t& r0, uint32_t& r1,
                                      uint32_t& r2, uint32_t& r3) {
    asm volatile("ldmatrix.sync.aligned.m8n8.x4.shared.b16 {%0,%1,%2,%3}, [%4];"
                 : "=r"(r0), "=r"(r1), "=r"(r2), "=r"(r3) : "r"(addr));
}
__device__ __forceinline__ void ldsm4t(uint32_t addr, uint32_t& r0, uint32_t& r1,
                                       uint32_t& r2, uint32_t& r3) {
    asm volatile("ldmatrix.sync.aligned.m8n8.x4.trans.shared.b16 {%0,%1,%2,%3}, [%4];"
                 : "=r"(r0), "=r"(r1), "=r"(r2), "=r"(r3) : "r"(addr));
}

__device__ __forceinline__ float block_sum(float v, float* red) {
    int tid = threadIdx.x, lane = tid & 31, warp = tid >> 5;
    int nw = blockDim.x >> 5;
    #pragma unroll
    for (int o = 16; o; o >>= 1) v += __shfl_xor_sync(0xffffffffu, v, o);
    if (lane == 0) red[warp] = v;
    __syncthreads();
    float r = (tid < nw) ? red[tid] : 0.0f;
    if (warp == 0) {
        #pragma unroll
        for (int o = 16; o; o >>= 1) r += __shfl_xor_sync(0xffffffffu, r, o);
        if (tid == 0) red[0] = r;
    }
    __syncthreads();
    float out = red[0];
    __syncthreads();
    return out;
}
__device__ __forceinline__ float block_max(float v, float* red) {
    int tid = threadIdx.x, lane = tid & 31, warp = tid >> 5;
    int nw = blockDim.x >> 5;
    #pragma unroll
    for (int o = 16; o; o >>= 1) v = fmaxf(v, __shfl_xor_sync(0xffffffffu, v, o));
    if (lane == 0) red[warp] = v;
    __syncthreads();
    float r = (tid < nw) ? red[tid] : -INFINITY;
    if (warp == 0) {
        #pragma unroll
        for (int o = 16; o; o >>= 1) r = fmaxf(r, __shfl_xor_sync(0xffffffffu, r, o));
        if (tid == 0) red[0] = r;
    }
    __syncthreads();
    float out = red[0];
    __syncthreads();
    return out;
}

// ---------------- embed + positional encoding -------------------------------
__global__ void embed_pe_kernel(const int* __restrict__ tokens,
                                const float* __restrict__ embed,
                                float* __restrict__ x, __half* __restrict__ x16) {
    const int row = blockIdx.x;
    const int t = row % T;
    const int tok = tokens[row];
    const float* erow = embed + (size_t)tok * D;
    float* xrow = x + (size_t)row * D;
    __half* xrow16 = x16 + (size_t)row * D;
    for (int i = threadIdx.x; i < D; i += blockDim.x) {
        int ip = i & ~1;
        double freq = exp(((double)ip / (double)D) * log(10000.0));
        double angle = (double)t / freq;
        float pe = (i & 1) ? (float)cos(angle) : (float)sin(angle);
        float v = erow[i] + pe;
        xrow[i] = v;
        xrow16[i] = __float2half(v);
    }
}

// ---------------- transpose fp32 -> fp16 [R,C] -> [C,R], batched -------------
__global__ void transpose_f2h_kernel(const float* __restrict__ in, __half* __restrict__ out,
                                     int R, int C, long inStride, long outStride) {
    __shared__ float tile[32][33];
    const long zi = blockIdx.z;
    in  += zi * inStride;
    out += zi * outStride;
    const int c0 = blockIdx.x * 32, r0 = blockIdx.y * 32;
    const int tx = threadIdx.x, ty = threadIdx.y;   // 32 x 8
    #pragma unroll
    for (int j = 0; j < 32; j += 8)
        tile[ty + j][tx] = in[(long)(r0 + ty + j) * C + c0 + tx];
    __syncthreads();
    #pragma unroll
    for (int j = 0; j < 32; j += 8)
        out[(long)(c0 + ty + j) * R + r0 + tx] = __float2half(tile[tx][ty + j]);
}

// ---------------- FP16 mma.sync GEMM -----------------------------------------
// C[M,N] = oscale * (A[M,K] @ B) (+bias)(+relu). A fp16 K-major [M,K].
// TRB=0: B = Bt [N,K] K-major (TT). TRB=1: B = [K,N] row-major (NN, trans ldmatrix).
// 128x128 CTA tile, 8 warps of 32x64, BK=64 (4x k16), 3-stage cp.async.
// CAUSAL: 0 none, 1 skip tiles above diagonal, 2 K truncated at bm+128.
#define RST 72                                   // A (and TT-B) row stride in halves (144 B)
#define RSTB 136                                 // NN B row stride in halves (272 B)
#define STAGE_H (256 * RST)                      // halves per stage
#define NSTAGE 3
#define GEMM_SMEM16 (NSTAGE * STAGE_H * 2)       // 110592 B

template<int CAUSAL, bool RELU, bool BIAS, bool OUT16, int TRB>
__global__ __launch_bounds__(256, 2) void gemm16(
    const __half* __restrict__ A, const __half* __restrict__ Bm,
    const float* __restrict__ b0, const float* __restrict__ b1, const float* __restrict__ b2,
    void* __restrict__ Cv, int N, int K, long sA, long sB, long sC, float oscale)
{
    extern __shared__ __half smh[];

    const int bm = blockIdx.y * 128;
    const int bn = blockIdx.x * 128;
    if (CAUSAL == 1 && bn > bm + 127) return;
    const int z = blockIdx.z;
    A  += (long)z * sA;
    Bm += (long)z * sB;

    const int tid = threadIdx.x, warp = tid >> 5, lane = tid & 31;
    const int g = lane >> 2, cg = lane & 3;
    const int wm = (warp >> 1) * 32, wn = (warp & 1) * 64;

    const int Kend = (CAUSAL == 2) ? min(K, bm + 128) : K;
    const int KT = Kend >> 6;

    const uint32_t sbase = smem_u32(smh);

    // per-lane ldmatrix byte offsets within a stage
    uint32_t aoff[2], boff[4];
    #pragma unroll
    for (int mi = 0; mi < 2; mi++)
        aoff[mi] = (uint32_t)((wm + mi * 16 + (lane & 15)) * RST * 2 + (lane >> 4) * 16);
    #pragma unroll
    for (int np = 0; np < 4; np++) {
        if (TRB == 0)
            boff[np] = (uint32_t)((128 + wn + np * 16 + (lane & 15)) * RST * 2 + (lane >> 4) * 16);
        else
            boff[np] = (uint32_t)(128 * RST * 2 + (lane & 15) * RSTB * 2
                                  + (wn + np * 16 + (lane >> 4) * 8) * 2);
    }
    constexpr uint32_t BKSTEP = (TRB == 0) ? 32u : (16u * RSTB * 2u);

    auto issue = [&](int s) {
        if (s >= KT) { cp_commit(); return; }
        const int k0 = s << 6;
        __half* As = smh + (s % NSTAGE) * STAGE_H;
        __half* Bs = As + 128 * RST;
        #pragma unroll
        for (int i = 0; i < 4; i++) {
            int idx = tid + i * 256;
            int r = idx >> 3, c = (idx & 7) * 8;
            cp16(&As[r * RST + c], A + (long)(bm + r) * K + k0 + c);
            if (TRB == 0) {
                cp16(&Bs[r * RST + c], Bm + (long)(bn + r) * K + k0 + c);
            } else {
                int rb = idx >> 4, cb = (idx & 15) * 8;   // 64 rows x 128 cols
                cp16(&Bs[rb * RSTB + cb], Bm + (long)(k0 + rb) * N + bn + cb);
            }
        }
        cp_commit();
    };

    float acc[2][8][4];
    #pragma unroll
    for (int mi = 0; mi < 2; mi++)
        #pragma unroll
        for (int ni = 0; ni < 8; ni++)
            #pragma unroll
            for (int j = 0; j < 4; j++) acc[mi][ni][j] = 0.0f;

    auto comp = [&](int slot) {
        const uint32_t st = sbase + (uint32_t)slot * (STAGE_H * 2);
        #pragma unroll
        for (int ks = 0; ks < 4; ks++) {
            uint32_t af[2][4];
            uint32_t bf[8][2];
            #pragma unroll
            for (int mi = 0; mi < 2; mi++)
                ldsm4(st + aoff[mi] + ks * 32, af[mi][0], af[mi][1], af[mi][2], af[mi][3]);
            #pragma unroll
            for (int np = 0; np < 4; np++) {
                uint32_t q0, q1, q2, q3;
                if (TRB == 0) {
                    ldsm4(st + boff[np] + ks * BKSTEP, q0, q1, q2, q3);
                    bf[2 * np][0] = q0; bf[2 * np][1] = q2;
                    bf[2 * np + 1][0] = q1; bf[2 * np + 1][1] = q3;
                } else {
                    ldsm4t(st + boff[np] + ks * BKSTEP, q0, q1, q2, q3);
                    bf[2 * np][0] = q0; bf[2 * np][1] = q1;
                    bf[2 * np + 1][0] = q2; bf[2 * np + 1][1] = q3;
                }
            }
            #pragma unroll
            for (int mi = 0; mi < 2; mi++)
                #pragma unroll
                for (int ni = 0; ni < 8; ni++)
                    asm volatile(
                        "mma.sync.aligned.m16n8k16.row.col.f32.f16.f16.f32 "
                        "{%0,%1,%2,%3}, {%4,%5,%6,%7}, {%8,%9}, {%0,%1,%2,%3};"
                        : "+f"(acc[mi][ni][0]), "+f"(acc[mi][ni][1]),
                          "+f"(acc[mi][ni][2]), "+f"(acc[mi][ni][3])
                        : "r"(af[mi][0]), "r"(af[mi][1]), "r"(af[mi][2]), "r"(af[mi][3]),
                          "r"(bf[ni][0]), "r"(bf[ni][1]));
        }
    };

    issue(0);
    issue(1);
    for (int i = 0; i < KT; i++) {
        cp_wait<1>();
        __syncthreads();
        issue(i + 2);
        comp(i % NSTAGE);
    }

    // epilogue
    const float* bias = BIAS ? (z == 0 ? b0 : (z == 1 ? b1 : b2)) : b0;
    float*  Cf = (float*)Cv  + (long)z * sC;
    __half* Ch = (__half*)Cv + (long)z * sC;
    #pragma unroll
    for (int mi = 0; mi < 2; mi++) {
        const long r0 = bm + wm + mi * 16 + g;
        #pragma unroll
        for (int ni = 0; ni < 8; ni++) {
            const int col = bn + wn + ni * 8 + cg * 2;
            float bb0 = 0.0f, bb1 = 0.0f;
            if (BIAS) { bb0 = bias[col]; bb1 = bias[col + 1]; }
            float2 v0 = make_float2(acc[mi][ni][0] * oscale + bb0, acc[mi][ni][1] * oscale + bb1);
            float2 v1 = make_float2(acc[mi][ni][2] * oscale + bb0, acc[mi][ni][3] * oscale + bb1);
            if (RELU) {
                v0.x = fmaxf(v0.x, 0.0f); v0.y = fmaxf(v0.y, 0.0f);
                v1.x = fmaxf(v1.x, 0.0f); v1.y = fmaxf(v1.y, 0.0f);
            }
            if (OUT16) {
                *(__half2*)(Ch + r0 * N + col)       = __floats2half2_rn(v0.x, v0.y);
                *(__half2*)(Ch + (r0 + 8) * N + col) = __floats2half2_rn(v1.x, v1.y);
            } else {
                *(float2*)(Cf + r0 * N + col)       = v0;
                *(float2*)(Cf + (r0 + 8) * N + col) = v1;
            }
        }
    }
}

// ---------------- causal softmax: fp16 scores -> fp16 probs ------------------
// scores already scaled by 1/sqrt(D) in the GEMM epilogue.
// zero-fill only up to the 128-aligned tile end (attnV truncates K there).
__global__ void softmax_causal_kernel(const __half* __restrict__ scores,
                                      __half* __restrict__ probs) {
    const int t = blockIdx.x;
    const int b = blockIdx.y;
    const __half* row = scores + ((size_t)b * T + t) * T;
    __half* prow = probs + ((size_t)b * T + t) * T;
    const int n = t + 1;
    const int zend = ((t >> 7) + 1) << 7;   // tile end = bm + 128
    __shared__ float red[32];
    const int tid = threadIdx.x;

    float m = -INFINITY;
    for (int s = tid; s < n; s += blockDim.x) m = fmaxf(m, __half2float(row[s]));
    m = block_max(m, red);

    float sum = 0.0f;
    for (int s = tid; s < n; s += blockDim.x) sum += expf(__half2float(row[s]) - m);
    sum = block_sum(sum, red);
    const float inv = 1.0f / sum;

    for (int s = tid; s < n; s += blockDim.x)
        prow[s] = __float2half(expf(__half2float(row[s]) - m) * inv);
    for (int s = n + tid; s < zend; s += blockDim.x) prow[s] = __float2half(0.0f);
}

// ---------------- x = LayerNorm(x + y) * g + beta  (vectorized) --------------
__global__ __launch_bounds__(256) void add_ln_kernel(
    float* __restrict__ x, __half* __restrict__ x16,
    const float* __restrict__ y,
    const float* __restrict__ g, const float* __restrict__ beta) {
    const int row = blockIdx.x;
    __shared__ float red[32];
    float* xr = x + (size_t)row * D;
    __half* xr16 = x16 + (size_t)row * D;
    const float* yr = y + (size_t)row * D;
    const int i = threadIdx.x * 4;         // 256 threads x 4 floats = 1024

    float4 xv = *(const float4*)(xr + i);
    float4 yv = *(const float4*)(yr + i);
    float4 v = make_float4(xv.x + yv.x, xv.y + yv.y, xv.z + yv.z, xv.w + yv.w);

    float sum = v.x + v.y + v.z + v.w;
    sum = block_sum(sum, red);
    const float mu = sum * (1.0f / D);

    float4 d = make_float4(v.x - mu, v.y - mu, v.z - mu, v.w - mu);
    float vs = d.x * d.x + d.y * d.y + d.z * d.z + d.w * d.w;
    vs = block_sum(vs, red);
    const float rstd = rsqrtf(vs * (1.0f / D) + 1e-5f);

    float4 gv = *(const float4*)(g + i);
    float4 bv = *(const float4*)(beta + i);
    float4 o = make_float4(d.x * rstd * gv.x + bv.x, d.y * rstd * gv.y + bv.y,
                           d.z * rstd * gv.z + bv.z, d.w * rstd * gv.w + bv.w);
    *(float4*)(xr + i) = o;
    __half2 h0 = __floats2half2_rn(o.x, o.y);
    __half2 h1 = __floats2half2_rn(o.z, o.w);
    *(__half2*)(xr16 + i) = h0;
    *(__half2*)(xr16 + i + 2) = h1;
}

// ---------------- in-place log_softmax over vocab ----------------------------
__global__ void log_softmax_kernel(float* __restrict__ out) {
    float* row = out + (size_t)blockIdx.x * V;
    __shared__ float red[32];
    const int tid = threadIdx.x;

    float m = -INFINITY, s = 0.0f;
    for (int i = tid; i < V; i += blockDim.x) {
        float v = row[i];
        if (v > m) { s = s * expf(m - v) + 1.0f; m = v; }
        else s += expf(v - m);
    }
    float M = block_max(m, red);
    float sum = block_sum(s * expf(m - M), red);
    const float lse = M + logf(sum);

    for (int i = tid; i < V; i += blockDim.x) row[i] -= lse;
}

// ---------------- launch -------------------------------------------------------
extern "C" void kernel_launch(void* const* d_in, const int* in_sizes, int n_in,
                              void* d_out, int out_size) {
    const int*   tokens = (const int*)  d_in[0];
    const float* embed  = (const float*)d_in[1];
    const float* Wq     = (const float*)d_in[2];
    const float* bq     = (const float*)d_in[3];
    const float* Wk     = (const float*)d_in[4];
    const float* bk     = (const float*)d_in[5];
    const float* Wv     = (const float*)d_in[6];
    const float* bv     = (const float*)d_in[7];
    const float* g1     = (const float*)d_in[8];
    const float* beta1  = (const float*)d_in[9];
    const float* W1     = (const float*)d_in[10];
    const float* bf1    = (const float*)d_in[11];
    const float* W2     = (const float*)d_in[12];
    const float* bf2    = (const float*)d_in[13];
    const float* g2     = (const float*)d_in[14];
    const float* beta2  = (const float*)d_in[15];
    const float* Wout   = (const float*)d_in[16];
    const float* bout   = (const float*)d_in[17];
    float* out = (float*)d_out;

    float *x, *attn;
    __half *x16, *qkv16, *scores16, *probs16, *h16, *wqkv16, *w1T16, *w2T16, *wout16;
    cudaGetSymbolAddress((void**)&x,        g_x);
    cudaGetSymbolAddress((void**)&x16,      g_x16);
    cudaGetSymbolAddress((void**)&qkv16,    g_qkv16);
    cudaGetSymbolAddress((void**)&attn,     g_attn);
    cudaGetSymbolAddress((void**)&scores16, g_scores16);
    cudaGetSymbolAddress((void**)&probs16,  g_probs16);
    cudaGetSymbolAddress((void**)&h16,      g_h16);
    cudaGetSymbolAddress((void**)&wqkv16,   g_wqkv16);
    cudaGetSymbolAddress((void**)&w1T16,    g_w1T16);
    cudaGetSymbolAddress((void**)&w2T16,    g_w2T16);
    cudaGetSymbolAddress((void**)&wout16,   g_wout16);
    __half* q16 = qkv16;
    __half* k16 = qkv16 + (size_t)BT * D;
    __half* v16 = qkv16 + (size_t)2 * BT * D;

    cudaFuncSetAttribute(gemm16<0, false, true,  true,  0>, cudaFuncAttributeMaxDynamicSharedMemorySize, GEMM_SMEM16);
    cudaFuncSetAttribute(gemm16<0, true,  true,  true,  0>, cudaFuncAttributeMaxDynamicSharedMemorySize, GEMM_SMEM16);
    cudaFuncSetAttribute(gemm16<0, false, true,  false, 0>, cudaFuncAttributeMaxDynamicSharedMemorySize, GEMM_SMEM16);
    cudaFuncSetAttribute(gemm16<1, false, false, true,  0>, cudaFuncAttributeMaxDynamicSharedMemorySize, GEMM_SMEM16);
    cudaFuncSetAttribute(gemm16<2, false, false, false, 1>, cudaFuncAttributeMaxDynamicSharedMemorySize, GEMM_SMEM16);

    dim3 tb(32, 8);
    // launches 1-5 (so the 6th launch ncu captures is the QKV GEMM)
    transpose_f2h_kernel<<<dim3(D / 32, D / 32, L), tb>>>(Wq, wqkv16 + 0 * (size_t)D * D, D, D, (long)D * D, (long)3 * D * D);
    transpose_f2h_kernel<<<dim3(D / 32, D / 32, L), tb>>>(Wk, wqkv16 + 1 * (size_t)D * D, D, D, (long)D * D, (long)3 * D * D);
    transpose_f2h_kernel<<<dim3(D / 32, D / 32, L), tb>>>(Wv, wqkv16 + 2 * (size_t)D * D, D, D, (long)D * D, (long)3 * D * D);
    transpose_f2h_kernel<<<dim3(DF / 32, D / 32, L), tb>>>(W1, w1T16, D, DF, (long)D * DF, (long)DF * D);
    embed_pe_kernel<<<BT, 256>>>(tokens, embed, x, x16);

    bool rest_transposed = false;

    for (int l = 0; l < L; ++l) {
        // fused QKV -> fp16 (z = 0,1,2 selects weight slice + bias + out slice)
        gemm16<0, false, true, true, 0><<<dim3(D / 128, BT / 128, 3), 256, GEMM_SMEM16>>>(
            x16, wqkv16 + (size_t)l * 3 * D * D,
            bq + (size_t)l * D, bk + (size_t)l * D, bv + (size_t)l * D,
            qkv16, D, D, 0, (long)D * D, (long)BT * D, 1.0f);

        if (!rest_transposed) {
            transpose_f2h_kernel<<<dim3(D / 32, DF / 32, L), tb>>>(W2, w2T16, DF, D, (long)DF * D, (long)D * DF);
            transpose_f2h_kernel<<<dim3(V / 32, D / 32, 1), tb>>>(Wout, wout16, D, V, 0, 0);
            rest_transposed = true;
        }

        // scores = (q @ k^T) / sqrt(D) -> fp16 (causal tile skip)
        gemm16<1, false, false, true, 0><<<dim3(T / 128, T / 128, B), 256, GEMM_SMEM16>>>(
            q16, k16, nullptr, nullptr, nullptr,
            scores16, T, D, (long)T * D, (long)T * D, (long)T * T, 0.03125f);

        softmax_causal_kernel<<<dim3(T, B, 1), 256>>>(scores16, probs16);

        // attn = probs @ V -> fp32 (NN-B via trans ldmatrix; K truncated at bm+128)
        gemm16<2, false, false, false, 1><<<dim3(D / 128, T / 128, B), 256, GEMM_SMEM16>>>(
            probs16, v16, nullptr, nullptr, nullptr,
            attn, D, T, (long)T * T, (long)T * D, (long)T * D, 1.0f);

        add_ln_kernel<<<BT, 256>>>(x, x16, attn, g1 + (size_t)l * D, beta1 + (size_t)l * D);

        // FFN1 -> fp16 h (relu)
        gemm16<0, true, true, true, 0><<<dim3(DF / 128, BT / 128, 1), 256, GEMM_SMEM16>>>(
            x16, w1T16 + (size_t)l * DF * D,
            bf1 + (size_t)l * DF, nullptr, nullptr,
            h16, DF, D, 0, 0, 0, 1.0f);
        // FFN2 -> fp32 attn
        gemm16<0, false, true, false, 0><<<dim3(D / 128, BT / 128, 1), 256, GEMM_SMEM16>>>(
            h16, w2T16 + (size_t)l * D * DF,
            bf2 + (size_t)l * D, nullptr, nullptr,
            attn, D, DF, 0, 0, 0, 1.0f);

        add_ln_kernel<<<BT, 256>>>(x, x16, attn, g2 + (size_t)l * D, beta2 + (size_t)l * D);
    }

    // vocab projection -> fp32 out
    gemm16<0, false, true, false, 0><<<dim3(V / 128, BT / 128, 1), 256, GEMM_SMEM16>>>(
        x16, wout16, bout, nullptr, nullptr,
        out, V, D, 0, 0, 0, 1.0f);
    log_softmax_kernel<<<BT, 256>>>(out);
}

// round 13
// speedup vs baseline: 1.1696x; 1.0313x over previous
#include <cuda_runtime.h>
#include <cuda_fp16.h>
#include <math.h>
#include <stdint.h>

#define B 2
#define T 2048
#define V 32000
#define D 1024
#define DF 4096
#define L 6
#define BT (B*T)

// ---------------- scratch (device globals; no allocation allowed) ----------
__device__ __align__(1024) float  g_x[(size_t)BT * D];
__device__ __align__(1024) __half g_x16[(size_t)BT * D];
__device__ __align__(1024) __half g_qkv16[(size_t)3 * BT * D];
__device__ __align__(1024) float  g_attn[(size_t)BT * D];
__device__ __align__(1024) __half g_scores16[(size_t)B * T * T];
__device__ __align__(1024) __half g_probs16[(size_t)B * T * T];
__device__ __align__(1024) __half g_h16[(size_t)BT * DF];
__device__ __align__(1024) __half g_logits16[(size_t)BT * V];
__device__ __align__(1024) __half g_wqkv16[(size_t)L * 3 * D * D];
__device__ __align__(1024) __half g_w1T16[(size_t)L * DF * D];
__device__ __align__(1024) __half g_w2T16[(size_t)L * D * DF];
__device__ __align__(1024) __half g_wout16[(size_t)V * D];

// ---------------- low-level helpers -----------------------------------------
__device__ __forceinline__ uint32_t smem_u32(const void* p) {
    uint32_t a;
    asm("{ .reg .u64 t; cvta.to.shared.u64 t, %1; cvt.u32.u64 %0, t; }" : "=r"(a) : "l"(p));
    return a;
}
__device__ __forceinline__ void cp16(void* smem_dst, const void* gmem_src) {
    uint32_t s = (uint32_t)__cvta_generic_to_shared(smem_dst);
    asm volatile("cp.async.cg.shared.global [%0], [%1], 16;" :: "r"(s), "l"(gmem_src));
}
__device__ __forceinline__ void cp_commit() {
    asm volatile("cp.async.commit_group;" ::: "memory");
}
template<int N>
__device__ __forceinline__ void cp_wait() {
    asm volatile("cp.async.wait_group %0;" :: "n"(N) : "memory");
}
__device__ __forceinline__ void ldsm4(uint32_t addr, uint32_t& r0, uint32_t& r1,
                                      uint32_t& r2, uint32_t& r3) {
    asm volatile("ldmatrix.sync.aligned.m8n8.x4.shared.b16 {%0,%1,%2,%3}, [%4];"
                 : "=r"(r0), "=r"(r1), "=r"(r2), "=r"(r3) : "r"(addr));
}
__device__ __forceinline__ void ldsm4t(uint32_t addr, uint32_t& r0, uint32_t& r1,
                                       uint32_t& r2, uint32_t& r3) {
    asm volatile("ldmatrix.sync.aligned.m8n8.x4.trans.shared.b16 {%0,%1,%2,%3}, [%4];"
                 : "=r"(r0), "=r"(r1), "=r"(r2), "=r"(r3) : "r"(addr));
}

__device__ __forceinline__ float block_sum(float v, float* red) {
    int tid = threadIdx.x, lane = tid & 31, warp = tid >> 5;
    int nw = blockDim.x >> 5;
    #pragma unroll
    for (int o = 16; o; o >>= 1) v += __shfl_xor_sync(0xffffffffu, v, o);
    if (lane == 0) red[warp] = v;
    __syncthreads();
    float r = (tid < nw) ? red[tid] : 0.0f;
    if (warp == 0) {
        #pragma unroll
        for (int o = 16; o; o >>= 1) r += __shfl_xor_sync(0xffffffffu, r, o);
        if (tid == 0) red[0] = r;
    }
    __syncthreads();
    float out = red[0];
    __syncthreads();
    return out;
}
__device__ __forceinline__ float block_max(float v, float* red) {
    int tid = threadIdx.x, lane = tid & 31, warp = tid >> 5;
    int nw = blockDim.x >> 5;
    #pragma unroll
    for (int o = 16; o; o >>= 1) v = fmaxf(v, __shfl_xor_sync(0xffffffffu, v, o));
    if (lane == 0) red[warp] = v;
    __syncthreads();
    float r = (tid < nw) ? red[tid] : -INFINITY;
    if (warp == 0) {
        #pragma unroll
        for (int o = 16; o; o >>= 1) r = fmaxf(r, __shfl_xor_sync(0xffffffffu, r, o));
        if (tid == 0) red[0] = r;
    }
    __syncthreads();
    float out = red[0];
    __syncthreads();
    return out;
}

// ---------------- embed + positional encoding -------------------------------
__global__ void embed_pe_kernel(const int* __restrict__ tokens,
                                const float* __restrict__ embed,
                                float* __restrict__ x, __half* __restrict__ x16) {
    const int row = blockIdx.x;
    const int t = row % T;
    const int tok = tokens[row];
    const float* erow = embed + (size_t)tok * D;
    float* xrow = x + (size_t)row * D;
    __half* xrow16 = x16 + (size_t)row * D;
    for (int i = threadIdx.x; i < D; i += blockDim.x) {
        int ip = i & ~1;
        double freq = exp(((double)ip / (double)D) * log(10000.0));
        double angle = (double)t / freq;
        float pe = (i & 1) ? (float)cos(angle) : (float)sin(angle);
        float v = erow[i] + pe;
        xrow[i] = v;
        xrow16[i] = __float2half(v);
    }
}

// ---------------- transpose fp32 -> fp16 [R,C] -> [C,R], batched -------------
__global__ void transpose_f2h_kernel(const float* __restrict__ in, __half* __restrict__ out,
                                     int R, int C, long inStride, long outStride) {
    __shared__ float tile[32][33];
    const long zi = blockIdx.z;
    in  += zi * inStride;
    out += zi * outStride;
    const int c0 = blockIdx.x * 32, r0 = blockIdx.y * 32;
    const int tx = threadIdx.x, ty = threadIdx.y;   // 32 x 8
    #pragma unroll
    for (int j = 0; j < 32; j += 8)
        tile[ty + j][tx] = in[(long)(r0 + ty + j) * C + c0 + tx];
    __syncthreads();
    #pragma unroll
    for (int j = 0; j < 32; j += 8)
        out[(long)(c0 + ty + j) * R + r0 + tx] = __float2half(tile[tx][ty + j]);
}

// ---------------- FP16 mma.sync GEMM -----------------------------------------
// C[M,N] = oscale * (A[M,K] @ B) (+bias)(+relu). A fp16 K-major [M,K].
// TRB=0: B = Bt [N,K] K-major (TT). TRB=1: B = [K,N] row-major (NN, trans ldmatrix).
// 128x128 CTA tile, 8 warps of 32x64, BK=64 (4x k16), 3-stage cp.async.
// CAUSAL: 0 none, 1 skip tiles above diagonal, 2 K truncated at bm+128.
#define RST 72                                   // A (and TT-B) row stride in halves (144 B)
#define RSTB 136                                 // NN B row stride in halves (272 B)
#define STAGE_H (256 * RST)                      // halves per stage
#define NSTAGE 3
#define GEMM_SMEM16 (NSTAGE * STAGE_H * 2)       // 110592 B

template<int CAUSAL, bool RELU, bool BIAS, bool OUT16, int TRB>
__global__ __launch_bounds__(256, 2) void gemm16(
    const __half* __restrict__ A, const __half* __restrict__ Bm,
    const float* __restrict__ b0, const float* __restrict__ b1, const float* __restrict__ b2,
    void* __restrict__ Cv, int N, int K, long sA, long sB, long sC, float oscale)
{
    extern __shared__ __half smh[];

    const int bm = blockIdx.y * 128;
    const int bn = blockIdx.x * 128;
    if (CAUSAL == 1 && bn > bm + 127) return;
    const int z = blockIdx.z;
    A  += (long)z * sA;
    Bm += (long)z * sB;

    const int tid = threadIdx.x, warp = tid >> 5, lane = tid & 31;
    const int g = lane >> 2, cg = lane & 3;
    const int wm = (warp >> 1) * 32, wn = (warp & 1) * 64;

    const int Kend = (CAUSAL == 2) ? min(K, bm + 128) : K;
    const int KT = Kend >> 6;

    const uint32_t sbase = smem_u32(smh);

    // per-lane ldmatrix byte offsets within a stage
    uint32_t aoff[2], boff[4];
    #pragma unroll
    for (int mi = 0; mi < 2; mi++)
        aoff[mi] = (uint32_t)((wm + mi * 16 + (lane & 15)) * RST * 2 + (lane >> 4) * 16);
    #pragma unroll
    for (int np = 0; np < 4; np++) {
        if (TRB == 0)
            boff[np] = (uint32_t)((128 + wn + np * 16 + (lane & 15)) * RST * 2 + (lane >> 4) * 16);
        else
            boff[np] = (uint32_t)(128 * RST * 2 + (lane & 15) * RSTB * 2
                                  + (wn + np * 16 + (lane >> 4) * 8) * 2);
    }
    constexpr uint32_t BKSTEP = (TRB == 0) ? 32u : (16u * RSTB * 2u);

    auto issue = [&](int s) {
        if (s >= KT) { cp_commit(); return; }
        const int k0 = s << 6;
        __half* As = smh + (s % NSTAGE) * STAGE_H;
        __half* Bs = As + 128 * RST;
        #pragma unroll
        for (int i = 0; i < 4; i++) {
            int idx = tid + i * 256;
            int r = idx >> 3, c = (idx & 7) * 8;
            cp16(&As[r * RST + c], A + (long)(bm + r) * K + k0 + c);
            if (TRB == 0) {
                cp16(&Bs[r * RST + c], Bm + (long)(bn + r) * K + k0 + c);
            } else {
                int rb = idx >> 4, cb = (idx & 15) * 8;   // 64 rows x 128 cols
                cp16(&Bs[rb * RSTB + cb], Bm + (long)(k0 + rb) * N + bn + cb);
            }
        }
        cp_commit();
    };

    float acc[2][8][4];
    #pragma unroll
    for (int mi = 0; mi < 2; mi++)
        #pragma unroll
        for (int ni = 0; ni < 8; ni++)
            #pragma unroll
            for (int j = 0; j < 4; j++) acc[mi][ni][j] = 0.0f;

    auto comp = [&](int slot) {
        const uint32_t st = sbase + (uint32_t)slot * (STAGE_H * 2);
        #pragma unroll
        for (int ks = 0; ks < 4; ks++) {
            uint32_t af[2][4];
            uint32_t bf[8][2];
            #pragma unroll
            for (int mi = 0; mi < 2; mi++)
                ldsm4(st + aoff[mi] + ks * 32, af[mi][0], af[mi][1], af[mi][2], af[mi][3]);
            #pragma unroll
            for (int np = 0; np < 4; np++) {
                uint32_t q0, q1, q2, q3;
                if (TRB == 0) {
                    ldsm4(st + boff[np] + ks * BKSTEP, q0, q1, q2, q3);
                    bf[2 * np][0] = q0; bf[2 * np][1] = q2;
                    bf[2 * np + 1][0] = q1; bf[2 * np + 1][1] = q3;
                } else {
                    ldsm4t(st + boff[np] + ks * BKSTEP, q0, q1, q2, q3);
                    bf[2 * np][0] = q0; bf[2 * np][1] = q1;
                    bf[2 * np + 1][0] = q2; bf[2 * np + 1][1] = q3;
                }
            }
            #pragma unroll
            for (int mi = 0; mi < 2; mi++)
                #pragma unroll
                for (int ni = 0; ni < 8; ni++)
                    asm volatile(
                        "mma.sync.aligned.m16n8k16.row.col.f32.f16.f16.f32 "
                        "{%0,%1,%2,%3}, {%4,%5,%6,%7}, {%8,%9}, {%0,%1,%2,%3};"
                        : "+f"(acc[mi][ni][0]), "+f"(acc[mi][ni][1]),
                          "+f"(acc[mi][ni][2]), "+f"(acc[mi][ni][3])
                        : "r"(af[mi][0]), "r"(af[mi][1]), "r"(af[mi][2]), "r"(af[mi][3]),
                          "r"(bf[ni][0]), "r"(bf[ni][1]));
        }
    };

    issue(0);
    issue(1);
    for (int i = 0; i < KT; i++) {
        cp_wait<1>();
        __syncthreads();
        issue(i + 2);
        comp(i % NSTAGE);
    }

    // epilogue
    const float* bias = BIAS ? (z == 0 ? b0 : (z == 1 ? b1 : b2)) : b0;
    float*  Cf = (float*)Cv  + (long)z * sC;
    __half* Ch = (__half*)Cv + (long)z * sC;
    #pragma unroll
    for (int mi = 0; mi < 2; mi++) {
        const long r0 = bm + wm + mi * 16 + g;
        #pragma unroll
        for (int ni = 0; ni < 8; ni++) {
            const int col = bn + wn + ni * 8 + cg * 2;
            float bb0 = 0.0f, bb1 = 0.0f;
            if (BIAS) { bb0 = bias[col]; bb1 = bias[col + 1]; }
            float2 v0 = make_float2(acc[mi][ni][0] * oscale + bb0, acc[mi][ni][1] * oscale + bb1);
            float2 v1 = make_float2(acc[mi][ni][2] * oscale + bb0, acc[mi][ni][3] * oscale + bb1);
            if (RELU) {
                v0.x = fmaxf(v0.x, 0.0f); v0.y = fmaxf(v0.y, 0.0f);
                v1.x = fmaxf(v1.x, 0.0f); v1.y = fmaxf(v1.y, 0.0f);
            }
            if (OUT16) {
                *(__half2*)(Ch + r0 * N + col)       = __floats2half2_rn(v0.x, v0.y);
                *(__half2*)(Ch + (r0 + 8) * N + col) = __floats2half2_rn(v1.x, v1.y);
            } else {
                *(float2*)(Cf + r0 * N + col)       = v0;
                *(float2*)(Cf + (r0 + 8) * N + col) = v1;
            }
        }
    }
}

// ---------------- causal softmax: fp16 scores -> fp16 probs ------------------
// scores already scaled by 1/sqrt(D) in the GEMM epilogue.
// Row cached in smem: 1 global read + 1 global write.
// zero-fill only up to the 128-aligned tile end (attnV truncates K there).
__global__ void softmax_causal_kernel(const __half* __restrict__ scores,
                                      __half* __restrict__ probs) {
    const int t = blockIdx.x;
    const int b = blockIdx.y;
    const __half* row = scores + ((size_t)b * T + t) * T;
    __half* prow = probs + ((size_t)b * T + t) * T;
    const int n = t + 1;
    const int zend = ((t >> 7) + 1) << 7;   // tile end = bm + 128
    __shared__ __half srow[T];
    __shared__ float red[32];
    const int tid = threadIdx.x;

    float m = -INFINITY;
    for (int s = tid; s < n; s += blockDim.x) {
        __half v = row[s];
        srow[s] = v;
        m = fmaxf(m, __half2float(v));
    }
    __syncthreads();
    m = block_max(m, red);

    float sum = 0.0f;
    for (int s = tid; s < n; s += blockDim.x) sum += expf(__half2float(srow[s]) - m);
    sum = block_sum(sum, red);
    const float inv = 1.0f / sum;

    for (int s = tid; s < n; s += blockDim.x)
        prow[s] = __float2half(expf(__half2float(srow[s]) - m) * inv);
    for (int s = n + tid; s < zend; s += blockDim.x) prow[s] = __float2half(0.0f);
}

// ---------------- x = LayerNorm(x + y) * g + beta  (vectorized) --------------
__global__ __launch_bounds__(256) void add_ln_kernel(
    float* __restrict__ x, __half* __restrict__ x16,
    const float* __restrict__ y,
    const float* __restrict__ g, const float* __restrict__ beta) {
    const int row = blockIdx.x;
    __shared__ float red[32];
    float* xr = x + (size_t)row * D;
    __half* xr16 = x16 + (size_t)row * D;
    const float* yr = y + (size_t)row * D;
    const int i = threadIdx.x * 4;         // 256 threads x 4 floats = 1024

    float4 xv = *(const float4*)(xr + i);
    float4 yv = *(const float4*)(yr + i);
    float4 v = make_float4(xv.x + yv.x, xv.y + yv.y, xv.z + yv.z, xv.w + yv.w);

    float sum = v.x + v.y + v.z + v.w;
    sum = block_sum(sum, red);
    const float mu = sum * (1.0f / D);

    float4 d = make_float4(v.x - mu, v.y - mu, v.z - mu, v.w - mu);
    float vs = d.x * d.x + d.y * d.y + d.z * d.z + d.w * d.w;
    vs = block_sum(vs, red);
    const float rstd = rsqrtf(vs * (1.0f / D) + 1e-5f);

    float4 gv = *(const float4*)(g + i);
    float4 bv = *(const float4*)(beta + i);
    float4 o = make_float4(d.x * rstd * gv.x + bv.x, d.y * rstd * gv.y + bv.y,
                           d.z * rstd * gv.z + bv.z, d.w * rstd * gv.w + bv.w);
    *(float4*)(xr + i) = o;
    __half2 h0 = __floats2half2_rn(o.x, o.y);
    __half2 h1 = __floats2half2_rn(o.z, o.w);
    *(__half2*)(xr16 + i) = h0;
    *(__half2*)(xr16 + i + 2) = h1;
}

// ---------------- log_softmax: fp16 logits -> fp32 out ------------------------
__global__ void log_softmax_kernel(const __half* __restrict__ logits,
                                   float* __restrict__ out) {
    const __half* row = logits + (size_t)blockIdx.x * V;
    float* orow = out + (size_t)blockIdx.x * V;
    __shared__ float red[32];
    const int tid = threadIdx.x;

    float m = -INFINITY, s = 0.0f;
    for (int i = tid * 2; i < V; i += blockDim.x * 2) {
        __half2 h = *(const __half2*)(row + i);
        float v0 = __low2float(h), v1 = __high2float(h);
        float mx = fmaxf(v0, v1);
        float e = expf(fminf(v0, v1) - mx) + 1.0f;
        if (mx > m) { s = s * expf(m - mx) + e; m = mx; }
        else s += e * expf(mx - m);
    }
    float M = block_max(m, red);
    float sum = block_sum(s * expf(m - M), red);
    const float lse = M + logf(sum);

    for (int i = tid * 2; i < V; i += blockDim.x * 2) {
        __half2 h = *(const __half2*)(row + i);
        float2 o = make_float2(__low2float(h) - lse, __high2float(h) - lse);
        *(float2*)(orow + i) = o;
    }
}

// ---------------- launch -------------------------------------------------------
extern "C" void kernel_launch(void* const* d_in, const int* in_sizes, int n_in,
                              void* d_out, int out_size) {
    const int*   tokens = (const int*)  d_in[0];
    const float* embed  = (const float*)d_in[1];
    const float* Wq     = (const float*)d_in[2];
    const float* bq     = (const float*)d_in[3];
    const float* Wk     = (const float*)d_in[4];
    const float* bk     = (const float*)d_in[5];
    const float* Wv     = (const float*)d_in[6];
    const float* bv     = (const float*)d_in[7];
    const float* g1     = (const float*)d_in[8];
    const float* beta1  = (const float*)d_in[9];
    const float* W1     = (const float*)d_in[10];
    const float* bf1    = (const float*)d_in[11];
    const float* W2     = (const float*)d_in[12];
    const float* bf2    = (const float*)d_in[13];
    const float* g2     = (const float*)d_in[14];
    const float* beta2  = (const float*)d_in[15];
    const float* Wout   = (const float*)d_in[16];
    const float* bout   = (const float*)d_in[17];
    float* out = (float*)d_out;

    float *x, *attn;
    __half *x16, *qkv16, *scores16, *probs16, *h16, *logits16, *wqkv16, *w1T16, *w2T16, *wout16;
    cudaGetSymbolAddress((void**)&x,        g_x);
    cudaGetSymbolAddress((void**)&x16,      g_x16);
    cudaGetSymbolAddress((void**)&qkv16,    g_qkv16);
    cudaGetSymbolAddress((void**)&attn,     g_attn);
    cudaGetSymbolAddress((void**)&scores16, g_scores16);
    cudaGetSymbolAddress((void**)&probs16,  g_probs16);
    cudaGetSymbolAddress((void**)&h16,      g_h16);
    cudaGetSymbolAddress((void**)&logits16, g_logits16);
    cudaGetSymbolAddress((void**)&wqkv16,   g_wqkv16);
    cudaGetSymbolAddress((void**)&w1T16,    g_w1T16);
    cudaGetSymbolAddress((void**)&w2T16,    g_w2T16);
    cudaGetSymbolAddress((void**)&wout16,   g_wout16);
    __half* q16 = qkv16;
    __half* k16 = qkv16 + (size_t)BT * D;
    __half* v16 = qkv16 + (size_t)2 * BT * D;

    cudaFuncSetAttribute(gemm16<0, false, true,  true,  0>, cudaFuncAttributeMaxDynamicSharedMemorySize, GEMM_SMEM16);
    cudaFuncSetAttribute(gemm16<0, true,  true,  true,  0>, cudaFuncAttributeMaxDynamicSharedMemorySize, GEMM_SMEM16);
    cudaFuncSetAttribute(gemm16<0, false, true,  false, 0>, cudaFuncAttributeMaxDynamicSharedMemorySize, GEMM_SMEM16);
    cudaFuncSetAttribute(gemm16<1, false, false, true,  0>, cudaFuncAttributeMaxDynamicSharedMemorySize, GEMM_SMEM16);
    cudaFuncSetAttribute(gemm16<2, false, false, false, 1>, cudaFuncAttributeMaxDynamicSharedMemorySize, GEMM_SMEM16);

    dim3 tb(32, 8);
    // launches 1-5 (so the 6th launch ncu captures is the QKV GEMM)
    transpose_f2h_kernel<<<dim3(D / 32, D / 32, L), tb>>>(Wq, wqkv16 + 0 * (size_t)D * D, D, D, (long)D * D, (long)3 * D * D);
    transpose_f2h_kernel<<<dim3(D / 32, D / 32, L), tb>>>(Wk, wqkv16 + 1 * (size_t)D * D, D, D, (long)D * D, (long)3 * D * D);
    transpose_f2h_kernel<<<dim3(D / 32, D / 32, L), tb>>>(Wv, wqkv16 + 2 * (size_t)D * D, D, D, (long)D * D, (long)3 * D * D);
    transpose_f2h_kernel<<<dim3(DF / 32, D / 32, L), tb>>>(W1, w1T16, D, DF, (long)D * DF, (long)DF * D);
    embed_pe_kernel<<<BT, 256>>>(tokens, embed, x, x16);

    bool rest_transposed = false;

    for (int l = 0; l < L; ++l) {
        // fused QKV -> fp16 (z = 0,1,2 selects weight slice + bias + out slice)
        gemm16<0, false, true, true, 0><<<dim3(D / 128, BT / 128, 3), 256, GEMM_SMEM16>>>(
            x16, wqkv16 + (size_t)l * 3 * D * D,
            bq + (size_t)l * D, bk + (size_t)l * D, bv + (size_t)l * D,
            qkv16, D, D, 0, (long)D * D, (long)BT * D, 1.0f);

        if (!rest_transposed) {
            transpose_f2h_kernel<<<dim3(D / 32, DF / 32, L), tb>>>(W2, w2T16, DF, D, (long)DF * D, (long)D * DF);
            transpose_f2h_kernel<<<dim3(V / 32, D / 32, 1), tb>>>(Wout, wout16, D, V, 0, 0);
            rest_transposed = true;
        }

        // scores = (q @ k^T) / sqrt(D) -> fp16 (causal tile skip)
        gemm16<1, false, false, true, 0><<<dim3(T / 128, T / 128, B), 256, GEMM_SMEM16>>>(
            q16, k16, nullptr, nullptr, nullptr,
            scores16, T, D, (long)T * D, (long)T * D, (long)T * T, 0.03125f);

        softmax_causal_kernel<<<dim3(T, B, 1), 256>>>(scores16, probs16);

        // attn = probs @ V -> fp32 (NN-B via trans ldmatrix; K truncated at bm+128)
        gemm16<2, false, false, false, 1><<<dim3(D / 128, T / 128, B), 256, GEMM_SMEM16>>>(
            probs16, v16, nullptr, nullptr, nullptr,
            attn, D, T, (long)T * T, (long)T * D, (long)T * D, 1.0f);

        add_ln_kernel<<<BT, 256>>>(x, x16, attn, g1 + (size_t)l * D, beta1 + (size_t)l * D);

        // FFN1 -> fp16 h (relu)
        gemm16<0, true, true, true, 0><<<dim3(DF / 128, BT / 128, 1), 256, GEMM_SMEM16>>>(
            x16, w1T16 + (size_t)l * DF * D,
            bf1 + (size_t)l * DF, nullptr, nullptr,
            h16, DF, D, 0, 0, 0, 1.0f);
        // FFN2 -> fp32 attn
        gemm16<0, false, true, false, 0><<<dim3(D / 128, BT / 128, 1), 256, GEMM_SMEM16>>>(
            h16, w2T16 + (size_t)l * D * DF,
            bf2 + (size_t)l * D, nullptr, nullptr,
            attn, D, DF, 0, 0, 0, 1.0f);

        add_ln_kernel<<<BT, 256>>>(x, x16, attn, g2 + (size_t)l * D, beta2 + (size_t)l * D);
    }

    // vocab projection -> fp16 logits, then log_softmax -> fp32 out
    gemm16<0, false, true, true, 0><<<dim3(V / 128, BT / 128, 1), 256, GEMM_SMEM16>>>(
        x16, wout16, bout, nullptr, nullptr,
        logits16, V, D, 0, 0, 0, 1.0f);
    log_softmax_kernel<<<BT, 256>>>(logits16, out);
}

// round 14
// speedup vs baseline: 1.2448x; 1.0642x over previous
#include <cuda_runtime.h>
#include <cuda_fp16.h>
#include <math.h>
#include <stdint.h>

#define B 2
#define T 2048
#define V 32000
#define D 1024
#define DF 4096
#define L 6
#define BT (B*T)

// ---------------- scratch (device globals; no allocation allowed) ----------
__device__ __align__(1024) float  g_x[(size_t)BT * D];
__device__ __align__(1024) __half g_x16[(size_t)BT * D];
__device__ __align__(1024) __half g_qkv16[(size_t)3 * BT * D];
__device__ __align__(1024) __half g_attn16[(size_t)BT * D];
__device__ __align__(1024) __half g_scores16[(size_t)B * T * T];
__device__ __align__(1024) __half g_probs16[(size_t)B * T * T];
__device__ __align__(1024) __half g_h16[(size_t)BT * DF];
__device__ __align__(1024) __half g_logits16[(size_t)BT * V];
__device__ __align__(1024) __half g_wqkv16[(size_t)L * 3 * D * D];
__device__ __align__(1024) __half g_w1T16[(size_t)L * DF * D];
__device__ __align__(1024) __half g_w2T16[(size_t)L * D * DF];
__device__ __align__(1024) __half g_wout16[(size_t)V * D];

// ---------------- low-level helpers -----------------------------------------
__device__ __forceinline__ uint32_t smem_u32(const void* p) {
    uint32_t a;
    asm("{ .reg .u64 t; cvta.to.shared.u64 t, %1; cvt.u32.u64 %0, t; }" : "=r"(a) : "l"(p));
    return a;
}
__device__ __forceinline__ void cp16(void* smem_dst, const void* gmem_src) {
    uint32_t s = (uint32_t)__cvta_generic_to_shared(smem_dst);
    asm volatile("cp.async.cg.shared.global [%0], [%1], 16;" :: "r"(s), "l"(gmem_src));
}
__device__ __forceinline__ void cp_commit() {
    asm volatile("cp.async.commit_group;" ::: "memory");
}
template<int N>
__device__ __forceinline__ void cp_wait() {
    asm volatile("cp.async.wait_group %0;" :: "n"(N) : "memory");
}
__device__ __forceinline__ void ldsm4(uint32_t addr, uint32_t& r0, uint32_t& r1,
                                      uint32_t& r2, uint32_t& r3) {
    asm volatile("ldmatrix.sync.aligned.m8n8.x4.shared.b16 {%0,%1,%2,%3}, [%4];"
                 : "=r"(r0), "=r"(r1), "=r"(r2), "=r"(r3) : "r"(addr));
}
__device__ __forceinline__ void ldsm4t(uint32_t addr, uint32_t& r0, uint32_t& r1,
                                       uint32_t& r2, uint32_t& r3) {
    asm volatile("ldmatrix.sync.aligned.m8n8.x4.trans.shared.b16 {%0,%1,%2,%3}, [%4];"
                 : "=r"(r0), "=r"(r1), "=r"(r2), "=r"(r3) : "r"(addr));
}

__device__ __forceinline__ float block_sum(float v, float* red) {
    int tid = threadIdx.x, lane = tid & 31, warp = tid >> 5;
    int nw = blockDim.x >> 5;
    #pragma unroll
    for (int o = 16; o; o >>= 1) v += __shfl_xor_sync(0xffffffffu, v, o);
    if (lane == 0) red[warp] = v;
    __syncthreads();
    float r = (tid < nw) ? red[tid] : 0.0f;
    if (warp == 0) {
        #pragma unroll
        for (int o = 16; o; o >>= 1) r += __shfl_xor_sync(0xffffffffu, r, o);
        if (tid == 0) red[0] = r;
    }
    __syncthreads();
    float out = red[0];
    __syncthreads();
    return out;
}
__device__ __forceinline__ float block_max(float v, float* red) {
    int tid = threadIdx.x, lane = tid & 31, warp = tid >> 5;
    int nw = blockDim.x >> 5;
    #pragma unroll
    for (int o = 16; o; o >>= 1) v = fmaxf(v, __shfl_xor_sync(0xffffffffu, v, o));
    if (lane == 0) red[warp] = v;
    __syncthreads();
    float r = (tid < nw) ? red[tid] : -INFINITY;
    if (warp == 0) {
        #pragma unroll
        for (int o = 16; o; o >>= 1) r = fmaxf(r, __shfl_xor_sync(0xffffffffu, r, o));
        if (tid == 0) red[0] = r;
    }
    __syncthreads();
    float out = red[0];
    __syncthreads();
    return out;
}

// ---------------- embed + positional encoding -------------------------------
// angle computed in double, range-reduced mod 2pi in double, trig in float.
__global__ void embed_pe_kernel(const int* __restrict__ tokens,
                                const float* __restrict__ embed,
                                float* __restrict__ x, __half* __restrict__ x16) {
    const int row = blockIdx.x;
    const int t = row % T;
    const int tok = tokens[row];
    const float* erow = embed + (size_t)tok * D;
    float* xrow = x + (size_t)row * D;
    __half* xrow16 = x16 + (size_t)row * D;
    const double TWO_PI = 6.283185307179586476925286766559;
    for (int i = threadIdx.x; i < D; i += blockDim.x) {
        int ip = i & ~1;
        double freq = exp(((double)ip / (double)D) * log(10000.0));
        double angle = (double)t / freq;
        double r = angle - floor(angle / TWO_PI) * TWO_PI;   // [0, 2pi)
        float rf = (float)r;
        float pe = (i & 1) ? cosf(rf) : sinf(rf);
        float v = erow[i] + pe;
        xrow[i] = v;
        xrow16[i] = __float2half(v);
    }
}

// ---------------- transpose fp32 -> fp16 [R,C] -> [C,R], batched -------------
__global__ void transpose_f2h_kernel(const float* __restrict__ in, __half* __restrict__ out,
                                     int R, int C, long inStride, long outStride) {
    __shared__ float tile[32][33];
    const long zi = blockIdx.z;
    in  += zi * inStride;
    out += zi * outStride;
    const int c0 = blockIdx.x * 32, r0 = blockIdx.y * 32;
    const int tx = threadIdx.x, ty = threadIdx.y;   // 32 x 8
    #pragma unroll
    for (int j = 0; j < 32; j += 8)
        tile[ty + j][tx] = in[(long)(r0 + ty + j) * C + c0 + tx];
    __syncthreads();
    #pragma unroll
    for (int j = 0; j < 32; j += 8)
        out[(long)(c0 + ty + j) * R + r0 + tx] = __float2half(tile[tx][ty + j]);
}

// ---------------- FP16 mma.sync GEMM -----------------------------------------
// C[M,N] = oscale * (A[M,K] @ B) (+bias)(+relu). A fp16 K-major [M,K].
// TRB=0: B = Bt [N,K] K-major (TT). TRB=1: B = [K,N] row-major (NN, trans ldmatrix).
// 128x128 CTA tile, 8 warps of 32x64, BK=64 (4x k16), 3-stage cp.async.
// CAUSAL: 0 none, 1 skip tiles above diagonal, 2 K truncated at bm+128.
#define RST 72                                   // A (and TT-B) row stride in halves (144 B)
#define RSTB 136                                 // NN B row stride in halves (272 B)
#define STAGE_H (256 * RST)                      // halves per stage
#define NSTAGE 3
#define GEMM_SMEM16 (NSTAGE * STAGE_H * 2)       // 110592 B

template<int CAUSAL, bool RELU, bool BIAS, bool OUT16, int TRB>
__global__ __launch_bounds__(256, 2) void gemm16(
    const __half* __restrict__ A, const __half* __restrict__ Bm,
    const float* __restrict__ b0, const float* __restrict__ b1, const float* __restrict__ b2,
    void* __restrict__ Cv, int N, int K, long sA, long sB, long sC, float oscale)
{
    extern __shared__ __half smh[];

    const int bm = blockIdx.y * 128;
    const int bn = blockIdx.x * 128;
    if (CAUSAL == 1 && bn > bm + 127) return;
    const int z = blockIdx.z;
    A  += (long)z * sA;
    Bm += (long)z * sB;

    const int tid = threadIdx.x, warp = tid >> 5, lane = tid & 31;
    const int g = lane >> 2, cg = lane & 3;
    const int wm = (warp >> 1) * 32, wn = (warp & 1) * 64;

    const int Kend = (CAUSAL == 2) ? min(K, bm + 128) : K;
    const int KT = Kend >> 6;

    const uint32_t sbase = smem_u32(smh);

    // per-lane ldmatrix byte offsets within a stage
    uint32_t aoff[2], boff[4];
    #pragma unroll
    for (int mi = 0; mi < 2; mi++)
        aoff[mi] = (uint32_t)((wm + mi * 16 + (lane & 15)) * RST * 2 + (lane >> 4) * 16);
    #pragma unroll
    for (int np = 0; np < 4; np++) {
        if (TRB == 0)
            boff[np] = (uint32_t)((128 + wn + np * 16 + (lane & 15)) * RST * 2 + (lane >> 4) * 16);
        else
            boff[np] = (uint32_t)(128 * RST * 2 + (lane & 15) * RSTB * 2
                                  + (wn + np * 16 + (lane >> 4) * 8) * 2);
    }
    constexpr uint32_t BKSTEP = (TRB == 0) ? 32u : (16u * RSTB * 2u);

    auto issue = [&](int s) {
        if (s >= KT) { cp_commit(); return; }
        const int k0 = s << 6;
        __half* As = smh + (s % NSTAGE) * STAGE_H;
        __half* Bs = As + 128 * RST;
        #pragma unroll
        for (int i = 0; i < 4; i++) {
            int idx = tid + i * 256;
            int r = idx >> 3, c = (idx & 7) * 8;
            cp16(&As[r * RST + c], A + (long)(bm + r) * K + k0 + c);
            if (TRB == 0) {
                cp16(&Bs[r * RST + c], Bm + (long)(bn + r) * K + k0 + c);
            } else {
                int rb = idx >> 4, cb = (idx & 15) * 8;   // 64 rows x 128 cols
                cp16(&Bs[rb * RSTB + cb], Bm + (long)(k0 + rb) * N + bn + cb);
            }
        }
        cp_commit();
    };

    float acc[2][8][4];
    #pragma unroll
    for (int mi = 0; mi < 2; mi++)
        #pragma unroll
        for (int ni = 0; ni < 8; ni++)
            #pragma unroll
            for (int j = 0; j < 4; j++) acc[mi][ni][j] = 0.0f;

    auto comp = [&](int slot) {
        const uint32_t st = sbase + (uint32_t)slot * (STAGE_H * 2);
        #pragma unroll
        for (int ks = 0; ks < 4; ks++) {
            uint32_t af[2][4];
            uint32_t bf[8][2];
            #pragma unroll
            for (int mi = 0; mi < 2; mi++)
                ldsm4(st + aoff[mi] + ks * 32, af[mi][0], af[mi][1], af[mi][2], af[mi][3]);
            #pragma unroll
            for (int np = 0; np < 4; np++) {
                uint32_t q0, q1, q2, q3;
                if (TRB == 0) {
                    ldsm4(st + boff[np] + ks * BKSTEP, q0, q1, q2, q3);
                    bf[2 * np][0] = q0; bf[2 * np][1] = q2;
                    bf[2 * np + 1][0] = q1; bf[2 * np + 1][1] = q3;
                } else {
                    ldsm4t(st + boff[np] + ks * BKSTEP, q0, q1, q2, q3);
                    bf[2 * np][0] = q0; bf[2 * np][1] = q1;
                    bf[2 * np + 1][0] = q2; bf[2 * np + 1][1] = q3;
                }
            }
            #pragma unroll
            for (int mi = 0; mi < 2; mi++)
                #pragma unroll
                for (int ni = 0; ni < 8; ni++)
                    asm volatile(
                        "mma.sync.aligned.m16n8k16.row.col.f32.f16.f16.f32 "
                        "{%0,%1,%2,%3}, {%4,%5,%6,%7}, {%8,%9}, {%0,%1,%2,%3};"
                        : "+f"(acc[mi][ni][0]), "+f"(acc[mi][ni][1]),
                          "+f"(acc[mi][ni][2]), "+f"(acc[mi][ni][3])
                        : "r"(af[mi][0]), "r"(af[mi][1]), "r"(af[mi][2]), "r"(af[mi][3]),
                          "r"(bf[ni][0]), "r"(bf[ni][1]));
        }
    };

    issue(0);
    issue(1);
    for (int i = 0; i < KT; i++) {
        cp_wait<1>();
        __syncthreads();
        issue(i + 2);
        comp(i % NSTAGE);
    }

    // epilogue
    const float* bias = BIAS ? (z == 0 ? b0 : (z == 1 ? b1 : b2)) : b0;
    float*  Cf = (float*)Cv  + (long)z * sC;
    __half* Ch = (__half*)Cv + (long)z * sC;
    #pragma unroll
    for (int mi = 0; mi < 2; mi++) {
        const long r0 = bm + wm + mi * 16 + g;
        #pragma unroll
        for (int ni = 0; ni < 8; ni++) {
            const int col = bn + wn + ni * 8 + cg * 2;
            float bb0 = 0.0f, bb1 = 0.0f;
            if (BIAS) { bb0 = bias[col]; bb1 = bias[col + 1]; }
            float2 v0 = make_float2(acc[mi][ni][0] * oscale + bb0, acc[mi][ni][1] * oscale + bb1);
            float2 v1 = make_float2(acc[mi][ni][2] * oscale + bb0, acc[mi][ni][3] * oscale + bb1);
            if (RELU) {
                v0.x = fmaxf(v0.x, 0.0f); v0.y = fmaxf(v0.y, 0.0f);
                v1.x = fmaxf(v1.x, 0.0f); v1.y = fmaxf(v1.y, 0.0f);
            }
            if (OUT16) {
                *(__half2*)(Ch + r0 * N + col)       = __floats2half2_rn(v0.x, v0.y);
                *(__half2*)(Ch + (r0 + 8) * N + col) = __floats2half2_rn(v1.x, v1.y);
            } else {
                *(float2*)(Cf + r0 * N + col)       = v0;
                *(float2*)(Cf + (r0 + 8) * N + col) = v1;
            }
        }
    }
}

// ---------------- causal softmax: fp16 scores -> fp16 probs ------------------
// scores already scaled by 1/sqrt(D) in the GEMM epilogue.
// Row cached in smem: 1 global read + 1 global write.
// zero-fill only up to the 128-aligned tile end (attnV truncates K there).
__global__ void softmax_causal_kernel(const __half* __restrict__ scores,
                                      __half* __restrict__ probs) {
    const int t = blockIdx.x;
    const int b = blockIdx.y;
    const __half* row = scores + ((size_t)b * T + t) * T;
    __half* prow = probs + ((size_t)b * T + t) * T;
    const int n = t + 1;
    const int zend = ((t >> 7) + 1) << 7;   // tile end = bm + 128
    __shared__ __half srow[T];
    __shared__ float red[32];
    const int tid = threadIdx.x;

    float m = -INFINITY;
    for (int s = tid; s < n; s += blockDim.x) {
        __half v = row[s];
        srow[s] = v;
        m = fmaxf(m, __half2float(v));
    }
    __syncthreads();
    m = block_max(m, red);

    float sum = 0.0f;
    for (int s = tid; s < n; s += blockDim.x) sum += expf(__half2float(srow[s]) - m);
    sum = block_sum(sum, red);
    const float inv = 1.0f / sum;

    for (int s = tid; s < n; s += blockDim.x)
        prow[s] = __float2half(expf(__half2float(srow[s]) - m) * inv);
    for (int s = n + tid; s < zend; s += blockDim.x) prow[s] = __float2half(0.0f);
}

// ---------------- x = LayerNorm(x + y16) * g + beta  (vectorized) ------------
__global__ __launch_bounds__(256) void add_ln_kernel(
    float* __restrict__ x, __half* __restrict__ x16,
    const __half* __restrict__ y,
    const float* __restrict__ g, const float* __restrict__ beta) {
    const int row = blockIdx.x;
    __shared__ float red[32];
    float* xr = x + (size_t)row * D;
    __half* xr16 = x16 + (size_t)row * D;
    const __half* yr = y + (size_t)row * D;
    const int i = threadIdx.x * 4;         // 256 threads x 4 floats = 1024

    float4 xv = *(const float4*)(xr + i);
    __half2 y0 = *(const __half2*)(yr + i);
    __half2 y1 = *(const __half2*)(yr + i + 2);
    float4 v = make_float4(xv.x + __low2float(y0), xv.y + __high2float(y0),
                           xv.z + __low2float(y1), xv.w + __high2float(y1));

    float sum = v.x + v.y + v.z + v.w;
    sum = block_sum(sum, red);
    const float mu = sum * (1.0f / D);

    float4 d = make_float4(v.x - mu, v.y - mu, v.z - mu, v.w - mu);
    float vs = d.x * d.x + d.y * d.y + d.z * d.z + d.w * d.w;
    vs = block_sum(vs, red);
    const float rstd = rsqrtf(vs * (1.0f / D) + 1e-5f);

    float4 gv = *(const float4*)(g + i);
    float4 bv = *(const float4*)(beta + i);
    float4 o = make_float4(d.x * rstd * gv.x + bv.x, d.y * rstd * gv.y + bv.y,
                           d.z * rstd * gv.z + bv.z, d.w * rstd * gv.w + bv.w);
    *(float4*)(xr + i) = o;
    *(__half2*)(xr16 + i)     = __floats2half2_rn(o.x, o.y);
    *(__half2*)(xr16 + i + 2) = __floats2half2_rn(o.z, o.w);
}

// ---------------- log_softmax: fp16 logits -> fp32 out (smem row cache) ------
__global__ void log_softmax_kernel(const __half* __restrict__ logits,
                                   float* __restrict__ out) {
    extern __shared__ __half srow[];      // V halves = 64000 B
    const __half* row = logits + (size_t)blockIdx.x * V;
    float* orow = out + (size_t)blockIdx.x * V;
    __shared__ float red[32];
    const int tid = threadIdx.x;

    float m = -INFINITY;
    for (int i = tid * 2; i < V; i += blockDim.x * 2) {
        __half2 h = *(const __half2*)(row + i);
        *(__half2*)(srow + i) = h;
        m = fmaxf(m, fmaxf(__low2float(h), __high2float(h)));
    }
    __syncthreads();
    float M = block_max(m, red);

    float s = 0.0f;
    for (int i = tid * 2; i < V; i += blockDim.x * 2) {
        __half2 h = *(const __half2*)(srow + i);
        s += expf(__low2float(h) - M) + expf(__high2float(h) - M);
    }
    float sum = block_sum(s, red);
    const float lse = M + logf(sum);

    for (int i = tid * 2; i < V; i += blockDim.x * 2) {
        __half2 h = *(const __half2*)(srow + i);
        float2 o = make_float2(__low2float(h) - lse, __high2float(h) - lse);
        *(float2*)(orow + i) = o;
    }
}

// ---------------- launch -------------------------------------------------------
extern "C" void kernel_launch(void* const* d_in, const int* in_sizes, int n_in,
                              void* d_out, int out_size) {
    const int*   tokens = (const int*)  d_in[0];
    const float* embed  = (const float*)d_in[1];
    const float* Wq     = (const float*)d_in[2];
    const float* bq     = (const float*)d_in[3];
    const float* Wk     = (const float*)d_in[4];
    const float* bk     = (const float*)d_in[5];
    const float* Wv     = (const float*)d_in[6];
    const float* bv     = (const float*)d_in[7];
    const float* g1     = (const float*)d_in[8];
    const float* beta1  = (const float*)d_in[9];
    const float* W1     = (const float*)d_in[10];
    const float* bf1    = (const float*)d_in[11];
    const float* W2     = (const float*)d_in[12];
    const float* bf2    = (const float*)d_in[13];
    const float* g2     = (const float*)d_in[14];
    const float* beta2  = (const float*)d_in[15];
    const float* Wout   = (const float*)d_in[16];
    const float* bout   = (const float*)d_in[17];
    float* out = (float*)d_out;

    float *x;
    __half *x16, *qkv16, *attn16, *scores16, *probs16, *h16, *logits16;
    __half *wqkv16, *w1T16, *w2T16, *wout16;
    cudaGetSymbolAddress((void**)&x,        g_x);
    cudaGetSymbolAddress((void**)&x16,      g_x16);
    cudaGetSymbolAddress((void**)&qkv16,    g_qkv16);
    cudaGetSymbolAddress((void**)&attn16,   g_attn16);
    cudaGetSymbolAddress((void**)&scores16, g_scores16);
    cudaGetSymbolAddress((void**)&probs16,  g_probs16);
    cudaGetSymbolAddress((void**)&h16,      g_h16);
    cudaGetSymbolAddress((void**)&logits16, g_logits16);
    cudaGetSymbolAddress((void**)&wqkv16,   g_wqkv16);
    cudaGetSymbolAddress((void**)&w1T16,    g_w1T16);
    cudaGetSymbolAddress((void**)&w2T16,    g_w2T16);
    cudaGetSymbolAddress((void**)&wout16,   g_wout16);
    __half* q16 = qkv16;
    __half* k16 = qkv16 + (size_t)BT * D;
    __half* v16 = qkv16 + (size_t)2 * BT * D;

    cudaFuncSetAttribute(gemm16<0, false, true,  true,  0>, cudaFuncAttributeMaxDynamicSharedMemorySize, GEMM_SMEM16);
    cudaFuncSetAttribute(gemm16<0, true,  true,  true,  0>, cudaFuncAttributeMaxDynamicSharedMemorySize, GEMM_SMEM16);
    cudaFuncSetAttribute(gemm16<1, false, false, true,  0>, cudaFuncAttributeMaxDynamicSharedMemorySize, GEMM_SMEM16);
    cudaFuncSetAttribute(gemm16<2, false, false, true,  1>, cudaFuncAttributeMaxDynamicSharedMemorySize, GEMM_SMEM16);
    cudaFuncSetAttribute(log_softmax_kernel, cudaFuncAttributeMaxDynamicSharedMemorySize, V * 2);

    dim3 tb(32, 8);
    // launches 1-5 (so the 6th launch ncu captures is the QKV GEMM)
    transpose_f2h_kernel<<<dim3(D / 32, D / 32, L), tb>>>(Wq, wqkv16 + 0 * (size_t)D * D, D, D, (long)D * D, (long)3 * D * D);
    transpose_f2h_kernel<<<dim3(D / 32, D / 32, L), tb>>>(Wk, wqkv16 + 1 * (size_t)D * D, D, D, (long)D * D, (long)3 * D * D);
    transpose_f2h_kernel<<<dim3(D / 32, D / 32, L), tb>>>(Wv, wqkv16 + 2 * (size_t)D * D, D, D, (long)D * D, (long)3 * D * D);
    transpose_f2h_kernel<<<dim3(DF / 32, D / 32, L), tb>>>(W1, w1T16, D, DF, (long)D * DF, (long)DF * D);
    embed_pe_kernel<<<BT, 256>>>(tokens, embed, x, x16);

    bool rest_transposed = false;

    for (int l = 0; l < L; ++l) {
        // fused QKV -> fp16 (z = 0,1,2 selects weight slice + bias + out slice)
        gemm16<0, false, true, true, 0><<<dim3(D / 128, BT / 128, 3), 256, GEMM_SMEM16>>>(
            x16, wqkv16 + (size_t)l * 3 * D * D,
            bq + (size_t)l * D, bk + (size_t)l * D, bv + (size_t)l * D,
            qkv16, D, D, 0, (long)D * D, (long)BT * D, 1.0f);

        if (!rest_transposed) {
            transpose_f2h_kernel<<<dim3(D / 32, DF / 32, L), tb>>>(W2, w2T16, DF, D, (long)DF * D, (long)D * DF);
            transpose_f2h_kernel<<<dim3(V / 32, D / 32, 1), tb>>>(Wout, wout16, D, V, 0, 0);
            rest_transposed = true;
        }

        // scores = (q @ k^T) / sqrt(D) -> fp16 (causal tile skip)
        gemm16<1, false, false, true, 0><<<dim3(T / 128, T / 128, B), 256, GEMM_SMEM16>>>(
            q16, k16, nullptr, nullptr, nullptr,
            scores16, T, D, (long)T * D, (long)T * D, (long)T * T, 0.03125f);

        softmax_causal_kernel<<<dim3(T, B, 1), 256>>>(scores16, probs16);

        // attn = probs @ V -> fp16 (NN-B via trans ldmatrix; K truncated at bm+128)
        gemm16<2, false, false, true, 1><<<dim3(D / 128, T / 128, B), 256, GEMM_SMEM16>>>(
            probs16, v16, nullptr, nullptr, nullptr,
            attn16, D, T, (long)T * T, (long)T * D, (long)T * D, 1.0f);

        add_ln_kernel<<<BT, 256>>>(x, x16, attn16, g1 + (size_t)l * D, beta1 + (size_t)l * D);

        // FFN1 -> fp16 h (relu)
        gemm16<0, true, true, true, 0><<<dim3(DF / 128, BT / 128, 1), 256, GEMM_SMEM16>>>(
            x16, w1T16 + (size_t)l * DF * D,
            bf1 + (size_t)l * DF, nullptr, nullptr,
            h16, DF, D, 0, 0, 0, 1.0f);
        // FFN2 -> fp16 attn
        gemm16<0, false, true, true, 0><<<dim3(D / 128, BT / 128, 1), 256, GEMM_SMEM16>>>(
            h16, w2T16 + (size_t)l * D * DF,
            bf2 + (size_t)l * D, nullptr, nullptr,
            attn16, D, DF, 0, 0, 0, 1.0f);

        add_ln_kernel<<<BT, 256>>>(x, x16, attn16, g2 + (size_t)l * D, beta2 + (size_t)l * D);
    }

    // vocab projection -> fp16 logits, then log_softmax -> fp32 out
    gemm16<0, false, true, true, 0><<<dim3(V / 128, BT / 128, 1), 256, GEMM_SMEM16>>>(
        x16, wout16, bout, nullptr, nullptr,
        logits16, V, D, 0, 0, 0, 1.0f);
    log_softmax_kernel<<<BT, 256, V * 2>>>(logits16, out);
}

// round 15
// speedup vs baseline: 1.2489x; 1.0033x over previous
#include <cuda_runtime.h>
#include <cuda_fp16.h>
#include <math.h>
#include <stdint.h>

#define B 2
#define T 2048
#define V 32000
#define D 1024
#define DF 4096
#define L 6
#define BT (B*T)

// ---------------- scratch (device globals; no allocation allowed) ----------
__device__ __align__(1024) float  g_x[(size_t)BT * D];
__device__ __align__(1024) __half g_x16[(size_t)BT * D];
__device__ __align__(1024) __half g_qkv16[(size_t)3 * BT * D];
__device__ __align__(1024) __half g_attn16[(size_t)BT * D];
__device__ __align__(1024) __half g_scores16[(size_t)B * T * T];
__device__ __align__(1024) __half g_probs16[(size_t)B * T * T];
__device__ __align__(1024) __half g_h16[(size_t)BT * DF];
__device__ __align__(1024) __half g_logits16[(size_t)BT * V];
__device__ __align__(1024) __half g_wqkv16[(size_t)L * 3 * D * D];
__device__ __align__(1024) __half g_w1T16[(size_t)L * DF * D];
__device__ __align__(1024) __half g_w2T16[(size_t)L * D * DF];
__device__ __align__(1024) __half g_wout16[(size_t)V * D];

// ---------------- low-level helpers -----------------------------------------
__device__ __forceinline__ uint32_t smem_u32(const void* p) {
    uint32_t a;
    asm("{ .reg .u64 t; cvta.to.shared.u64 t, %1; cvt.u32.u64 %0, t; }" : "=r"(a) : "l"(p));
    return a;
}
__device__ __forceinline__ void cp16(void* smem_dst, const void* gmem_src) {
    uint32_t s = (uint32_t)__cvta_generic_to_shared(smem_dst);
    asm volatile("cp.async.cg.shared.global [%0], [%1], 16;" :: "r"(s), "l"(gmem_src));
}
__device__ __forceinline__ void cp_commit() {
    asm volatile("cp.async.commit_group;" ::: "memory");
}
template<int N>
__device__ __forceinline__ void cp_wait() {
    asm volatile("cp.async.wait_group %0;" :: "n"(N) : "memory");
}
__device__ __forceinline__ void ldsm4(uint32_t addr, uint32_t& r0, uint32_t& r1,
                                      uint32_t& r2, uint32_t& r3) {
    asm volatile("ldmatrix.sync.aligned.m8n8.x4.shared.b16 {%0,%1,%2,%3}, [%4];"
                 : "=r"(r0), "=r"(r1), "=r"(r2), "=r"(r3) : "r"(addr));
}
__device__ __forceinline__ void ldsm4t(uint32_t addr, uint32_t& r0, uint32_t& r1,
                                       uint32_t& r2, uint32_t& r3) {
    asm volatile("ldmatrix.sync.aligned.m8n8.x4.trans.shared.b16 {%0,%1,%2,%3}, [%4];"
                 : "=r"(r0), "=r"(r1), "=r"(r2), "=r"(r3) : "r"(addr));
}

__device__ __forceinline__ float block_sum(float v, float* red) {
    int tid = threadIdx.x, lane = tid & 31, warp = tid >> 5;
    int nw = blockDim.x >> 5;
    #pragma unroll
    for (int o = 16; o; o >>= 1) v += __shfl_xor_sync(0xffffffffu, v, o);
    if (lane == 0) red[warp] = v;
    __syncthreads();
    float r = (tid < nw) ? red[tid] : 0.0f;
    if (warp == 0) {
        #pragma unroll
        for (int o = 16; o; o >>= 1) r += __shfl_xor_sync(0xffffffffu, r, o);
        if (tid == 0) red[0] = r;
    }
    __syncthreads();
    float out = red[0];
    __syncthreads();
    return out;
}
__device__ __forceinline__ float block_max(float v, float* red) {
    int tid = threadIdx.x, lane = tid & 31, warp = tid >> 5;
    int nw = blockDim.x >> 5;
    #pragma unroll
    for (int o = 16; o; o >>= 1) v = fmaxf(v, __shfl_xor_sync(0xffffffffu, v, o));
    if (lane == 0) red[warp] = v;
    __syncthreads();
    float r = (tid < nw) ? red[tid] : -INFINITY;
    if (warp == 0) {
        #pragma unroll
        for (int o = 16; o; o >>= 1) r = fmaxf(r, __shfl_xor_sync(0xffffffffu, r, o));
        if (tid == 0) red[0] = r;
    }
    __syncthreads();
    float out = red[0];
    __syncthreads();
    return out;
}

// ---------------- embed + positional encoding -------------------------------
__global__ void embed_pe_kernel(const int* __restrict__ tokens,
                                const float* __restrict__ embed,
                                float* __restrict__ x, __half* __restrict__ x16) {
    const int row = blockIdx.x;
    const int t = row % T;
    const int tok = tokens[row];
    const float* erow = embed + (size_t)tok * D;
    float* xrow = x + (size_t)row * D;
    __half* xrow16 = x16 + (size_t)row * D;
    const double TWO_PI = 6.283185307179586476925286766559;
    for (int i = threadIdx.x; i < D; i += blockDim.x) {
        int ip = i & ~1;
        double freq = exp(((double)ip / (double)D) * log(10000.0));
        double angle = (double)t / freq;
        double r = angle - floor(angle / TWO_PI) * TWO_PI;   // [0, 2pi)
        float rf = (float)r;
        float pe = (i & 1) ? cosf(rf) : sinf(rf);
        float v = erow[i] + pe;
        xrow[i] = v;
        xrow16[i] = __float2half(v);
    }
}

// ---------------- transpose fp32 -> fp16 [R,C] -> [C,R], batched -------------
__global__ void transpose_f2h_kernel(const float* __restrict__ in, __half* __restrict__ out,
                                     int R, int C, long inStride, long outStride) {
    __shared__ float tile[32][33];
    const long zi = blockIdx.z;
    in  += zi * inStride;
    out += zi * outStride;
    const int c0 = blockIdx.x * 32, r0 = blockIdx.y * 32;
    const int tx = threadIdx.x, ty = threadIdx.y;   // 32 x 8
    #pragma unroll
    for (int j = 0; j < 32; j += 8)
        tile[ty + j][tx] = in[(long)(r0 + ty + j) * C + c0 + tx];
    __syncthreads();
    #pragma unroll
    for (int j = 0; j < 32; j += 8)
        out[(long)(c0 + ty + j) * R + r0 + tx] = __float2half(tile[tx][ty + j]);
}

// ---------------- FP16 mma.sync GEMM -----------------------------------------
// C[M,N] = oscale * (A[M,K] @ B) (+bias)(+relu). A fp16 K-major [M,K].
// TRB=0: B = Bt [N,K] K-major (TT). TRB=1: B = [K,N] row-major (NN, trans ldmatrix).
// SWAP=1: bm from blockIdx.x, bn from blockIdx.y (L2 B-tile reuse for tall grids).
// 128x128 CTA tile, 8 warps of 32x64, BK=64 (4x k16), 3-stage cp.async.
// CAUSAL: 0 none, 1 skip tiles above diagonal, 2 K truncated at bm+128.
#define RST 72                                   // A (and TT-B) row stride in halves (144 B)
#define RSTB 136                                 // NN B row stride in halves (272 B)
#define STAGE_H (256 * RST)                      // halves per stage
#define NSTAGE 3
#define GEMM_SMEM16 (NSTAGE * STAGE_H * 2)       // 110592 B

template<int CAUSAL, bool RELU, bool BIAS, bool OUT16, int TRB, int SWAP = 0>
__global__ __launch_bounds__(256, 2) void gemm16(
    const __half* __restrict__ A, const __half* __restrict__ Bm,
    const float* __restrict__ b0, const float* __restrict__ b1, const float* __restrict__ b2,
    void* __restrict__ Cv, int N, int K, long sA, long sB, long sC, float oscale)
{
    extern __shared__ __half smh[];

    const int bm = (SWAP ? blockIdx.x : blockIdx.y) * 128;
    const int bn = (SWAP ? blockIdx.y : blockIdx.x) * 128;
    if (CAUSAL == 1 && bn > bm + 127) return;
    const int z = blockIdx.z;
    A  += (long)z * sA;
    Bm += (long)z * sB;

    const int tid = threadIdx.x, warp = tid >> 5, lane = tid & 31;
    const int g = lane >> 2, cg = lane & 3;
    const int wm = (warp >> 1) * 32, wn = (warp & 1) * 64;

    const int Kend = (CAUSAL == 2) ? min(K, bm + 128) : K;
    const int KT = Kend >> 6;

    const uint32_t sbase = smem_u32(smh);

    // per-lane ldmatrix byte offsets within a stage
    uint32_t aoff[2], boff[4];
    #pragma unroll
    for (int mi = 0; mi < 2; mi++)
        aoff[mi] = (uint32_t)((wm + mi * 16 + (lane & 15)) * RST * 2 + (lane >> 4) * 16);
    #pragma unroll
    for (int np = 0; np < 4; np++) {
        if (TRB == 0)
            boff[np] = (uint32_t)((128 + wn + np * 16 + (lane & 15)) * RST * 2 + (lane >> 4) * 16);
        else
            boff[np] = (uint32_t)(128 * RST * 2 + (lane & 15) * RSTB * 2
                                  + (wn + np * 16 + (lane >> 4) * 8) * 2);
    }
    constexpr uint32_t BKSTEP = (TRB == 0) ? 32u : (16u * RSTB * 2u);

    auto issue = [&](int s) {
        if (s >= KT) { cp_commit(); return; }
        const int k0 = s << 6;
        __half* As = smh + (s % NSTAGE) * STAGE_H;
        __half* Bs = As + 128 * RST;
        #pragma unroll
        for (int i = 0; i < 4; i++) {
            int idx = tid + i * 256;
            int r = idx >> 3, c = (idx & 7) * 8;
            cp16(&As[r * RST + c], A + (long)(bm + r) * K + k0 + c);
            if (TRB == 0) {
                cp16(&Bs[r * RST + c], Bm + (long)(bn + r) * K + k0 + c);
            } else {
                int rb = idx >> 4, cb = (idx & 15) * 8;   // 64 rows x 128 cols
                cp16(&Bs[rb * RSTB + cb], Bm + (long)(k0 + rb) * N + bn + cb);
            }
        }
        cp_commit();
    };

    float acc[2][8][4];
    #pragma unroll
    for (int mi = 0; mi < 2; mi++)
        #pragma unroll
        for (int ni = 0; ni < 8; ni++)
            #pragma unroll
            for (int j = 0; j < 4; j++) acc[mi][ni][j] = 0.0f;

    auto comp = [&](int slot) {
        const uint32_t st = sbase + (uint32_t)slot * (STAGE_H * 2);
        #pragma unroll
        for (int ks = 0; ks < 4; ks++) {
            uint32_t af[2][4];
            uint32_t bf[8][2];
            #pragma unroll
            for (int mi = 0; mi < 2; mi++)
                ldsm4(st + aoff[mi] + ks * 32, af[mi][0], af[mi][1], af[mi][2], af[mi][3]);
            #pragma unroll
            for (int np = 0; np < 4; np++) {
                uint32_t q0, q1, q2, q3;
                if (TRB == 0) {
                    ldsm4(st + boff[np] + ks * BKSTEP, q0, q1, q2, q3);
                    bf[2 * np][0] = q0; bf[2 * np][1] = q2;
                    bf[2 * np + 1][0] = q1; bf[2 * np + 1][1] = q3;
                } else {
                    ldsm4t(st + boff[np] + ks * BKSTEP, q0, q1, q2, q3);
                    bf[2 * np][0] = q0; bf[2 * np][1] = q1;
                    bf[2 * np + 1][0] = q2; bf[2 * np + 1][1] = q3;
                }
            }
            #pragma unroll
            for (int mi = 0; mi < 2; mi++)
                #pragma unroll
                for (int ni = 0; ni < 8; ni++)
                    asm volatile(
                        "mma.sync.aligned.m16n8k16.row.col.f32.f16.f16.f32 "
                        "{%0,%1,%2,%3}, {%4,%5,%6,%7}, {%8,%9}, {%0,%1,%2,%3};"
                        : "+f"(acc[mi][ni][0]), "+f"(acc[mi][ni][1]),
                          "+f"(acc[mi][ni][2]), "+f"(acc[mi][ni][3])
                        : "r"(af[mi][0]), "r"(af[mi][1]), "r"(af[mi][2]), "r"(af[mi][3]),
                          "r"(bf[ni][0]), "r"(bf[ni][1]));
        }
    };

    issue(0);
    issue(1);
    for (int i = 0; i < KT; i++) {
        cp_wait<1>();
        __syncthreads();
        issue(i + 2);
        comp(i % NSTAGE);
    }

    // epilogue
    const float* bias = BIAS ? (z == 0 ? b0 : (z == 1 ? b1 : b2)) : b0;
    float*  Cf = (float*)Cv  + (long)z * sC;
    __half* Ch = (__half*)Cv + (long)z * sC;
    #pragma unroll
    for (int mi = 0; mi < 2; mi++) {
        const long r0 = bm + wm + mi * 16 + g;
        #pragma unroll
        for (int ni = 0; ni < 8; ni++) {
            const int col = bn + wn + ni * 8 + cg * 2;
            float bb0 = 0.0f, bb1 = 0.0f;
            if (BIAS) { bb0 = bias[col]; bb1 = bias[col + 1]; }
            float2 v0 = make_float2(acc[mi][ni][0] * oscale + bb0, acc[mi][ni][1] * oscale + bb1);
            float2 v1 = make_float2(acc[mi][ni][2] * oscale + bb0, acc[mi][ni][3] * oscale + bb1);
            if (RELU) {
                v0.x = fmaxf(v0.x, 0.0f); v0.y = fmaxf(v0.y, 0.0f);
                v1.x = fmaxf(v1.x, 0.0f); v1.y = fmaxf(v1.y, 0.0f);
            }
            if (OUT16) {
                *(__half2*)(Ch + r0 * N + col)       = __floats2half2_rn(v0.x, v0.y);
                *(__half2*)(Ch + (r0 + 8) * N + col) = __floats2half2_rn(v1.x, v1.y);
            } else {
                *(float2*)(Cf + r0 * N + col)       = v0;
                *(float2*)(Cf + (r0 + 8) * N + col) = v1;
            }
        }
    }
}

// ---------------- causal softmax: fp16 scores -> fp16 probs ------------------
__global__ void softmax_causal_kernel(const __half* __restrict__ scores,
                                      __half* __restrict__ probs) {
    const int t = blockIdx.x;
    const int b = blockIdx.y;
    const __half* row = scores + ((size_t)b * T + t) * T;
    __half* prow = probs + ((size_t)b * T + t) * T;
    const int n = t + 1;
    const int zend = ((t >> 7) + 1) << 7;   // tile end = bm + 128
    __shared__ __half srow[T];
    __shared__ float red[32];
    const int tid = threadIdx.x;

    float m = -INFINITY;
    for (int s = tid; s < n; s += blockDim.x) {
        __half v = row[s];
        srow[s] = v;
        m = fmaxf(m, __half2float(v));
    }
    __syncthreads();
    m = block_max(m, red);

    float sum = 0.0f;
    for (int s = tid; s < n; s += blockDim.x) sum += expf(__half2float(srow[s]) - m);
    sum = block_sum(sum, red);
    const float inv = 1.0f / sum;

    for (int s = tid; s < n; s += blockDim.x)
        prow[s] = __float2half(expf(__half2float(srow[s]) - m) * inv);
    for (int s = n + tid; s < zend; s += blockDim.x) prow[s] = __float2half(0.0f);
}

// ---------------- x = LayerNorm(x + y16) * g + beta  (vectorized) ------------
__global__ __launch_bounds__(256) void add_ln_kernel(
    float* __restrict__ x, __half* __restrict__ x16,
    const __half* __restrict__ y,
    const float* __restrict__ g, const float* __restrict__ beta) {
    const int row = blockIdx.x;
    __shared__ float red[32];
    float* xr = x + (size_t)row * D;
    __half* xr16 = x16 + (size_t)row * D;
    const __half* yr = y + (size_t)row * D;
    const int i = threadIdx.x * 4;         // 256 threads x 4 floats = 1024

    float4 xv = *(const float4*)(xr + i);
    __half2 y0 = *(const __half2*)(yr + i);
    __half2 y1 = *(const __half2*)(yr + i + 2);
    float4 v = make_float4(xv.x + __low2float(y0), xv.y + __high2float(y0),
                           xv.z + __low2float(y1), xv.w + __high2float(y1));

    float sum = v.x + v.y + v.z + v.w;
    sum = block_sum(sum, red);
    const float mu = sum * (1.0f / D);

    float4 d = make_float4(v.x - mu, v.y - mu, v.z - mu, v.w - mu);
    float vs = d.x * d.x + d.y * d.y + d.z * d.z + d.w * d.w;
    vs = block_sum(vs, red);
    const float rstd = rsqrtf(vs * (1.0f / D) + 1e-5f);

    float4 gv = *(const float4*)(g + i);
    float4 bv = *(const float4*)(beta + i);
    float4 o = make_float4(d.x * rstd * gv.x + bv.x, d.y * rstd * gv.y + bv.y,
                           d.z * rstd * gv.z + bv.z, d.w * rstd * gv.w + bv.w);
    *(float4*)(xr + i) = o;
    *(__half2*)(xr16 + i)     = __floats2half2_rn(o.x, o.y);
    *(__half2*)(xr16 + i + 2) = __floats2half2_rn(o.z, o.w);
}

// ---------------- log_softmax: fp16 logits -> fp32 out (smem row cache) ------
__global__ void log_softmax_kernel(const __half* __restrict__ logits,
                                   float* __restrict__ out) {
    extern __shared__ __half srow[];      // V halves = 64000 B
    const __half* row = logits + (size_t)blockIdx.x * V;
    float* orow = out + (size_t)blockIdx.x * V;
    __shared__ float red[32];
    const int tid = threadIdx.x;

    float m = -INFINITY;
    for (int i = tid * 2; i < V; i += blockDim.x * 2) {
        __half2 h = *(const __half2*)(row + i);
        *(__half2*)(srow + i) = h;
        m = fmaxf(m, fmaxf(__low2float(h), __high2float(h)));
    }
    __syncthreads();
    float M = block_max(m, red);

    float s = 0.0f;
    for (int i = tid * 2; i < V; i += blockDim.x * 2) {
        __half2 h = *(const __half2*)(srow + i);
        s += expf(__low2float(h) - M) + expf(__high2float(h) - M);
    }
    float sum = block_sum(s, red);
    const float lse = M + logf(sum);

    for (int i = tid * 2; i < V; i += blockDim.x * 2) {
        __half2 h = *(const __half2*)(srow + i);
        float2 o = make_float2(__low2float(h) - lse, __high2float(h) - lse);
        *(float2*)(orow + i) = o;
    }
}

// ---------------- launch -------------------------------------------------------
extern "C" void kernel_launch(void* const* d_in, const int* in_sizes, int n_in,
                              void* d_out, int out_size) {
    const int*   tokens = (const int*)  d_in[0];
    const float* embed  = (const float*)d_in[1];
    const float* Wq     = (const float*)d_in[2];
    const float* bq     = (const float*)d_in[3];
    const float* Wk     = (const float*)d_in[4];
    const float* bk     = (const float*)d_in[5];
    const float* Wv     = (const float*)d_in[6];
    const float* bv     = (const float*)d_in[7];
    const float* g1     = (const float*)d_in[8];
    const float* beta1  = (const float*)d_in[9];
    const float* W1     = (const float*)d_in[10];
    const float* bf1    = (const float*)d_in[11];
    const float* W2     = (const float*)d_in[12];
    const float* bf2    = (const float*)d_in[13];
    const float* g2     = (const float*)d_in[14];
    const float* beta2  = (const float*)d_in[15];
    const float* Wout   = (const float*)d_in[16];
    const float* bout   = (const float*)d_in[17];
    float* out = (float*)d_out;

    float *x;
    __half *x16, *qkv16, *attn16, *scores16, *probs16, *h16, *logits16;
    __half *wqkv16, *w1T16, *w2T16, *wout16;
    cudaGetSymbolAddress((void**)&x,        g_x);
    cudaGetSymbolAddress((void**)&x16,      g_x16);
    cudaGetSymbolAddress((void**)&qkv16,    g_qkv16);
    cudaGetSymbolAddress((void**)&attn16,   g_attn16);
    cudaGetSymbolAddress((void**)&scores16, g_scores16);
    cudaGetSymbolAddress((void**)&probs16,  g_probs16);
    cudaGetSymbolAddress((void**)&h16,      g_h16);
    cudaGetSymbolAddress((void**)&logits16, g_logits16);
    cudaGetSymbolAddress((void**)&wqkv16,   g_wqkv16);
    cudaGetSymbolAddress((void**)&w1T16,    g_w1T16);
    cudaGetSymbolAddress((void**)&w2T16,    g_w2T16);
    cudaGetSymbolAddress((void**)&wout16,   g_wout16);
    __half* q16 = qkv16;
    __half* k16 = qkv16 + (size_t)BT * D;
    __half* v16 = qkv16 + (size_t)2 * BT * D;

    cudaFuncSetAttribute(gemm16<0, false, true,  true,  0, 0>, cudaFuncAttributeMaxDynamicSharedMemorySize, GEMM_SMEM16);
    cudaFuncSetAttribute(gemm16<0, true,  true,  true,  0, 0>, cudaFuncAttributeMaxDynamicSharedMemorySize, GEMM_SMEM16);
    cudaFuncSetAttribute(gemm16<0, false, true,  true,  0, 1>, cudaFuncAttributeMaxDynamicSharedMemorySize, GEMM_SMEM16);
    cudaFuncSetAttribute(gemm16<1, false, false, true,  0, 0>, cudaFuncAttributeMaxDynamicSharedMemorySize, GEMM_SMEM16);
    cudaFuncSetAttribute(gemm16<2, false, false, true,  1, 0>, cudaFuncAttributeMaxDynamicSharedMemorySize, GEMM_SMEM16);
    cudaFuncSetAttribute(log_softmax_kernel, cudaFuncAttributeMaxDynamicSharedMemorySize, V * 2);

    dim3 tb(32, 8);
    // launches 1-5 (so the 6th launch ncu captures is the QKV GEMM)
    transpose_f2h_kernel<<<dim3(D / 32, D / 32, L), tb>>>(Wq, wqkv16 + 0 * (size_t)D * D, D, D, (long)D * D, (long)3 * D * D);
    transpose_f2h_kernel<<<dim3(D / 32, D / 32, L), tb>>>(Wk, wqkv16 + 1 * (size_t)D * D, D, D, (long)D * D, (long)3 * D * D);
    transpose_f2h_kernel<<<dim3(D / 32, D / 32, L), tb>>>(Wv, wqkv16 + 2 * (size_t)D * D, D, D, (long)D * D, (long)3 * D * D);
    transpose_f2h_kernel<<<dim3(DF / 32, D / 32, L), tb>>>(W1, w1T16, D, DF, (long)D * DF, (long)DF * D);
    embed_pe_kernel<<<BT, 256>>>(tokens, embed, x, x16);

    bool rest_transposed = false;

    for (int l = 0; l < L; ++l) {
        // fused QKV -> fp16 (z = 0,1,2 selects weight slice + bias + out slice)
        gemm16<0, false, true, true, 0, 0><<<dim3(D / 128, BT / 128, 3), 256, GEMM_SMEM16>>>(
            x16, wqkv16 + (size_t)l * 3 * D * D,
            bq + (size_t)l * D, bk + (size_t)l * D, bv + (size_t)l * D,
            qkv16, D, D, 0, (long)D * D, (long)BT * D, 1.0f);

        if (!rest_transposed) {
            transpose_f2h_kernel<<<dim3(D / 32, DF / 32, L), tb>>>(W2, w2T16, DF, D, (long)DF * D, (long)D * DF);
            transpose_f2h_kernel<<<dim3(V / 32, D / 32, 1), tb>>>(Wout, wout16, D, V, 0, 0);
            rest_transposed = true;
        }

        // scores = (q @ k^T) / sqrt(D) -> fp16 (causal tile skip)
        gemm16<1, false, false, true, 0, 0><<<dim3(T / 128, T / 128, B), 256, GEMM_SMEM16>>>(
            q16, k16, nullptr, nullptr, nullptr,
            scores16, T, D, (long)T * D, (long)T * D, (long)T * T, 0.03125f);

        softmax_causal_kernel<<<dim3(T, B, 1), 256>>>(scores16, probs16);

        // attn = probs @ V -> fp16 (NN-B via trans ldmatrix; K truncated at bm+128)
        gemm16<2, false, false, true, 1, 0><<<dim3(D / 128, T / 128, B), 256, GEMM_SMEM16>>>(
            probs16, v16, nullptr, nullptr, nullptr,
            attn16, D, T, (long)T * T, (long)T * D, (long)T * D, 1.0f);

        add_ln_kernel<<<BT, 256>>>(x, x16, attn16, g1 + (size_t)l * D, beta1 + (size_t)l * D);

        // FFN1 -> fp16 h (relu)
        gemm16<0, true, true, true, 0, 0><<<dim3(DF / 128, BT / 128, 1), 256, GEMM_SMEM16>>>(
            x16, w1T16 + (size_t)l * DF * D,
            bf1 + (size_t)l * DF, nullptr, nullptr,
            h16, DF, D, 0, 0, 0, 1.0f);
        // FFN2 -> fp16 attn
        gemm16<0, false, true, true, 0, 0><<<dim3(D / 128, BT / 128, 1), 256, GEMM_SMEM16>>>(
            h16, w2T16 + (size_t)l * D * DF,
            bf2 + (size_t)l * D, nullptr, nullptr,
            attn16, D, DF, 0, 0, 0, 1.0f);

        add_ln_kernel<<<BT, 256>>>(x, x16, attn16, g2 + (size_t)l * D, beta2 + (size_t)l * D);
    }

    // vocab projection -> fp16 logits (SWAP grid: M-tiles fastest for L2 B reuse)
    gemm16<0, false, true, true, 0, 1><<<dim3(BT / 128, V / 128, 1), 256, GEMM_SMEM16>>>(
        x16, wout16, bout, nullptr, nullptr,
        logits16, V, D, 0, 0, 0, 1.0f);
    log_softmax_kernel<<<BT, 512, V * 2>>>(logits16, out);
}

// round 17
// speedup vs baseline: 1.4245x; 1.1406x over previous
#include <cuda_runtime.h>
#include <cuda_fp16.h>
#include <math.h>
#include <stdint.h>

#define B 2
#define T 2048
#define V 32000
#define D 1024
#define DF 4096
#define L 6
#define BT (B*T)

// ---------------- scratch (device globals; no allocation allowed) ----------
__device__ __align__(1024) __half g_x16[(size_t)BT * D];
__device__ __align__(1024) __half g_qkv16[(size_t)3 * BT * D];
__device__ __align__(1024) __half g_attn16[(size_t)BT * D];
__device__ __align__(1024) __half g_scores16[(size_t)B * T * T];
__device__ __align__(1024) __half g_probs16[(size_t)B * T * T];
__device__ __align__(1024) __half g_h16[(size_t)BT * DF];
__device__ __align__(1024) __half g_logits16[(size_t)BT * V];
__device__ __align__(1024) __half g_wqkv16[(size_t)L * 3 * D * D];
__device__ __align__(1024) __half g_w1T16[(size_t)L * DF * D];
__device__ __align__(1024) __half g_w2T16[(size_t)L * D * DF];
__device__ __align__(1024) __half g_wout16[(size_t)V * D];

// ---------------- low-level helpers -----------------------------------------
__device__ __forceinline__ uint32_t smem_u32(const void* p) {
    uint32_t a;
    asm("{ .reg .u64 t; cvta.to.shared.u64 t, %1; cvt.u32.u64 %0, t; }" : "=r"(a) : "l"(p));
    return a;
}
__device__ __forceinline__ void cp16(void* smem_dst, const void* gmem_src) {
    uint32_t s = (uint32_t)__cvta_generic_to_shared(smem_dst);
    asm volatile("cp.async.cg.shared.global [%0], [%1], 16;" :: "r"(s), "l"(gmem_src));
}
__device__ __forceinline__ void cp_commit() {
    asm volatile("cp.async.commit_group;" ::: "memory");
}
template<int N>
__device__ __forceinline__ void cp_wait() {
    asm volatile("cp.async.wait_group %0;" :: "n"(N) : "memory");
}
__device__ __forceinline__ void ldsm4(uint32_t addr, uint32_t& r0, uint32_t& r1,
                                      uint32_t& r2, uint32_t& r3) {
    asm volatile("ldmatrix.sync.aligned.m8n8.x4.shared.b16 {%0,%1,%2,%3}, [%4];"
                 : "=r"(r0), "=r"(r1), "=r"(r2), "=r"(r3) : "r"(addr));
}
__device__ __forceinline__ void ldsm4t(uint32_t addr, uint32_t& r0, uint32_t& r1,
                                       uint32_t& r2, uint32_t& r3) {
    asm volatile("ldmatrix.sync.aligned.m8n8.x4.trans.shared.b16 {%0,%1,%2,%3}, [%4];"
                 : "=r"(r0), "=r"(r1), "=r"(r2), "=r"(r3) : "r"(addr));
}

__device__ __forceinline__ float block_sum(float v, float* red) {
    int tid = threadIdx.x, lane = tid & 31, warp = tid >> 5;
    int nw = blockDim.x >> 5;
    #pragma unroll
    for (int o = 16; o; o >>= 1) v += __shfl_xor_sync(0xffffffffu, v, o);
    if (lane == 0) red[warp] = v;
    __syncthreads();
    float r = (tid < nw) ? red[tid] : 0.0f;
    if (warp == 0) {
        #pragma unroll
        for (int o = 16; o; o >>= 1) r += __shfl_xor_sync(0xffffffffu, r, o);
        if (tid == 0) red[0] = r;
    }
    __syncthreads();
    float out = red[0];
    __syncthreads();
    return out;
}
__device__ __forceinline__ float block_max(float v, float* red) {
    int tid = threadIdx.x, lane = tid & 31, warp = tid >> 5;
    int nw = blockDim.x >> 5;
    #pragma unroll
    for (int o = 16; o; o >>= 1) v = fmaxf(v, __shfl_xor_sync(0xffffffffu, v, o));
    if (lane == 0) red[warp] = v;
    __syncthreads();
    float r = (tid < nw) ? red[tid] : -INFINITY;
    if (warp == 0) {
        #pragma unroll
        for (int o = 16; o; o >>= 1) r = fmaxf(r, __shfl_xor_sync(0xffffffffu, r, o));
        if (tid == 0) red[0] = r;
    }
    __syncthreads();
    float out = red[0];
    __syncthreads();
    return out;
}

// ---------------- embed + positional encoding (fp32, matches reference) ------
__global__ void embed_pe_kernel(const int* __restrict__ tokens,
                                const float* __restrict__ embed,
                                __half* __restrict__ x16) {
    const int row = blockIdx.x;
    const int t = row % T;
    const int tok = tokens[row];
    const float* erow = embed + (size_t)tok * D;
    __half* xrow16 = x16 + (size_t)row * D;
    for (int i = threadIdx.x; i < D; i += blockDim.x) {
        int ip = i & ~1;
        float freq = powf(10000.0f, (float)ip / (float)D);
        float angle = (float)t / freq;
        float pe = (i & 1) ? cosf(angle) : sinf(angle);
        xrow16[i] = __float2half(erow[i] + pe);
    }
}

// ---------------- transpose fp32 -> fp16, 64x32 tiles, int4 stores -----------
// in: [R, C] fp32.  out: [C, R] fp16.  grid: (C/32, R/64, Z); block (32, 8)
__global__ void transpose_f2h_kernel(const float* __restrict__ in, __half* __restrict__ out,
                                     int R, int C, long inStride, long outStride) {
    __shared__ float tile[64][33];
    const long zi = blockIdx.z;
    in  += zi * inStride;
    out += zi * outStride;
    const int c0 = blockIdx.x * 32, r0 = blockIdx.y * 64;
    const int tx = threadIdx.x, ty = threadIdx.y;
    #pragma unroll
    for (int j = 0; j < 64; j += 8)
        tile[ty + j][tx] = in[(long)(r0 + ty + j) * C + c0 + tx];
    __syncthreads();
    const int tid = ty * 32 + tx;
    const int oc = tid >> 3, ob = (tid & 7) * 8;
    __half tmp[8];
    #pragma unroll
    for (int j = 0; j < 8; j++) tmp[j] = __float2half(tile[ob + j][oc]);
    *(int4*)(out + (long)(c0 + oc) * R + r0 + ob) = *(int4*)tmp;
}

// ---------------- FP16 mma.sync GEMM -----------------------------------------
// C[M,N] = oscale * (A[M,K] @ B) (+bias)(+relu). A fp16 K-major [M,K].
// TRB=0: B = Bt [N,K] K-major (TT). TRB=1: B = [K,N] row-major (NN, trans ldmatrix).
// SWAP=1: bm from blockIdx.x, bn from blockIdx.y.
// 128x128 CTA tile, 8 warps of 32x64, BK=64 (4x k16), 3-stage cp.async.
// CAUSAL: 0 none, 1 skip tiles above diagonal, 2 K truncated at bm+128.
#define RST 72
#define RSTB 136
#define STAGE_H (256 * RST)
#define NSTAGE 3
#define GEMM_SMEM16 (NSTAGE * STAGE_H * 2)       // 110592 B

template<int CAUSAL, bool RELU, bool BIAS, bool OUT16, int TRB, int SWAP = 0>
__global__ __launch_bounds__(256, 2) void gemm16(
    const __half* __restrict__ A, const __half* __restrict__ Bm,
    const float* __restrict__ b0, const float* __restrict__ b1, const float* __restrict__ b2,
    void* __restrict__ Cv, int N, int K, long sA, long sB, long sC, float oscale)
{
    extern __shared__ __half smh[];

    const int bm = (SWAP ? blockIdx.x : blockIdx.y) * 128;
    const int bn = (SWAP ? blockIdx.y : blockIdx.x) * 128;
    if (CAUSAL == 1 && bn > bm + 127) return;
    const int z = blockIdx.z;
    A  += (long)z * sA;
    Bm += (long)z * sB;

    const int tid = threadIdx.x, warp = tid >> 5, lane = tid & 31;
    const int g = lane >> 2, cg = lane & 3;
    const int wm = (warp >> 1) * 32, wn = (warp & 1) * 64;

    const int Kend = (CAUSAL == 2) ? min(K, bm + 128) : K;
    const int KT = Kend >> 6;

    const uint32_t sbase = smem_u32(smh);

    uint32_t aoff[2], boff[4];
    #pragma unroll
    for (int mi = 0; mi < 2; mi++)
        aoff[mi] = (uint32_t)((wm + mi * 16 + (lane & 15)) * RST * 2 + (lane >> 4) * 16);
    #pragma unroll
    for (int np = 0; np < 4; np++) {
        if (TRB == 0)
            boff[np] = (uint32_t)((128 + wn + np * 16 + (lane & 15)) * RST * 2 + (lane >> 4) * 16);
        else
            boff[np] = (uint32_t)(128 * RST * 2 + (lane & 15) * RSTB * 2
                                  + (wn + np * 16 + (lane >> 4) * 8) * 2);
    }
    constexpr uint32_t BKSTEP = (TRB == 0) ? 32u : (16u * RSTB * 2u);

    auto issue = [&](int s) {
        if (s >= KT) { cp_commit(); return; }
        const int k0 = s << 6;
        __half* As = smh + (s % NSTAGE) * STAGE_H;
        __half* Bs = As + 128 * RST;
        #pragma unroll
        for (int i = 0; i < 4; i++) {
            int idx = tid + i * 256;
            int r = idx >> 3, c = (idx & 7) * 8;
            cp16(&As[r * RST + c], A + (long)(bm + r) * K + k0 + c);
            if (TRB == 0) {
                cp16(&Bs[r * RST + c], Bm + (long)(bn + r) * K + k0 + c);
            } else {
                int rb = idx >> 4, cb = (idx & 15) * 8;
                cp16(&Bs[rb * RSTB + cb], Bm + (long)(k0 + rb) * N + bn + cb);
            }
        }
        cp_commit();
    };

    float acc[2][8][4];
    #pragma unroll
    for (int mi = 0; mi < 2; mi++)
        #pragma unroll
        for (int ni = 0; ni < 8; ni++)
            #pragma unroll
            for (int j = 0; j < 4; j++) acc[mi][ni][j] = 0.0f;

    auto comp = [&](int slot) {
        const uint32_t st = sbase + (uint32_t)slot * (STAGE_H * 2);
        #pragma unroll
        for (int ks = 0; ks < 4; ks++) {
            uint32_t af[2][4];
            uint32_t bf[8][2];
            #pragma unroll
            for (int mi = 0; mi < 2; mi++)
                ldsm4(st + aoff[mi] + ks * 32, af[mi][0], af[mi][1], af[mi][2], af[mi][3]);
            #pragma unroll
            for (int np = 0; np < 4; np++) {
                uint32_t q0, q1, q2, q3;
                if (TRB == 0) {
                    ldsm4(st + boff[np] + ks * BKSTEP, q0, q1, q2, q3);
                    bf[2 * np][0] = q0; bf[2 * np][1] = q2;
                    bf[2 * np + 1][0] = q1; bf[2 * np + 1][1] = q3;
                } else {
                    ldsm4t(st + boff[np] + ks * BKSTEP, q0, q1, q2, q3);
                    bf[2 * np][0] = q0; bf[2 * np][1] = q1;
                    bf[2 * np + 1][0] = q2; bf[2 * np + 1][1] = q3;
                }
            }
            #pragma unroll
            for (int mi = 0; mi < 2; mi++)
                #pragma unroll
                for (int ni = 0; ni < 8; ni++)
                    asm volatile(
                        "mma.sync.aligned.m16n8k16.row.col.f32.f16.f16.f32 "
                        "{%0,%1,%2,%3}, {%4,%5,%6,%7}, {%8,%9}, {%0,%1,%2,%3};"
                        : "+f"(acc[mi][ni][0]), "+f"(acc[mi][ni][1]),
                          "+f"(acc[mi][ni][2]), "+f"(acc[mi][ni][3])
                        : "r"(af[mi][0]), "r"(af[mi][1]), "r"(af[mi][2]), "r"(af[mi][3]),
                          "r"(bf[ni][0]), "r"(bf[ni][1]));
        }
    };

    issue(0);
    issue(1);
    for (int i = 0; i < KT; i++) {
        cp_wait<1>();
        __syncthreads();
        issue(i + 2);
        comp(i % NSTAGE);
    }

    // epilogue
    const float* bias = BIAS ? (z == 0 ? b0 : (z == 1 ? b1 : b2)) : b0;
    float*  Cf = (float*)Cv  + (long)z * sC;
    __half* Ch = (__half*)Cv + (long)z * sC;
    #pragma unroll
    for (int mi = 0; mi < 2; mi++) {
        const long r0 = bm + wm + mi * 16 + g;
        #pragma unroll
        for (int ni = 0; ni < 8; ni++) {
            const int col = bn + wn + ni * 8 + cg * 2;
            float bb0 = 0.0f, bb1 = 0.0f;
            if (BIAS) { bb0 = bias[col]; bb1 = bias[col + 1]; }
            float2 v0 = make_float2(acc[mi][ni][0] * oscale + bb0, acc[mi][ni][1] * oscale + bb1);
            float2 v1 = make_float2(acc[mi][ni][2] * oscale + bb0, acc[mi][ni][3] * oscale + bb1);
            if (RELU) {
                v0.x = fmaxf(v0.x, 0.0f); v0.y = fmaxf(v0.y, 0.0f);
                v1.x = fmaxf(v1.x, 0.0f); v1.y = fmaxf(v1.y, 0.0f);
            }
            if (OUT16) {
                *(__half2*)(Ch + r0 * N + col)       = __floats2half2_rn(v0.x, v0.y);
                *(__half2*)(Ch + (r0 + 8) * N + col) = __floats2half2_rn(v1.x, v1.y);
            } else {
                *(float2*)(Cf + r0 * N + col)       = v0;
                *(float2*)(Cf + (r0 + 8) * N + col) = v1;
            }
        }
    }
}

// ---------------- causal softmax: register-resident, int4 I/O ----------------
// 256 threads x 8 halves cover the whole <=2048 row. One read, one write.
__global__ void softmax_causal_kernel(const __half* __restrict__ scores,
                                      __half* __restrict__ probs) {
    const int t = blockIdx.x;
    const int b = blockIdx.y;
    const __half* row = scores + ((size_t)b * T + t) * T;
    __half* prow = probs + ((size_t)b * T + t) * T;
    const int n = t + 1;
    const int zend = ((t >> 7) + 1) << 7;   // 128-aligned tile end (attnV K-limit)
    __shared__ float red[32];
    const int tid = threadIdx.x;
    const int s0 = tid * 8;
    const bool active = s0 < zend;

    float f[8];
    float m = -INFINITY;
    if (active) {
        __half h[8];
        *(int4*)h = *(const int4*)(row + s0);
        #pragma unroll
        for (int j = 0; j < 8; j++) {
            f[j] = __half2float(h[j]);
            if (s0 + j < n) m = fmaxf(m, f[j]);
        }
    }
    const float M = block_max(m, red);

    float s = 0.0f;
    if (active) {
        #pragma unroll
        for (int j = 0; j < 8; j++) {
            float e = (s0 + j < n) ? expf(f[j] - M) : 0.0f;
            f[j] = e;
            s += e;
        }
    }
    const float inv = 1.0f / block_sum(s, red);

    if (active) {
        __half o[8];
        #pragma unroll
        for (int j = 0; j < 8; j++) o[j] = __float2half(f[j] * inv);
        *(int4*)(prow + s0) = *(int4*)o;
    }
}

// ---------------- x16 = LayerNorm(x16 + y16) * g + beta ----------------------
__global__ __launch_bounds__(256) void add_ln_kernel(
    __half* __restrict__ x16, const __half* __restrict__ y,
    const float* __restrict__ g, const float* __restrict__ beta) {
    const int row = blockIdx.x;
    __shared__ float red[32];
    __half* xr16 = x16 + (size_t)row * D;
    const __half* yr = y + (size_t)row * D;
    const int i = threadIdx.x * 4;

    __half2 x0 = *(const __half2*)(xr16 + i);
    __half2 x1 = *(const __half2*)(xr16 + i + 2);
    __half2 y0 = *(const __half2*)(yr + i);
    __half2 y1 = *(const __half2*)(yr + i + 2);
    float4 v = make_float4(__low2float(x0) + __low2float(y0),
                           __high2float(x0) + __high2float(y0),
                           __low2float(x1) + __low2float(y1),
                           __high2float(x1) + __high2float(y1));

    float sum = v.x + v.y + v.z + v.w;
    sum = block_sum(sum, red);
    const float mu = sum * (1.0f / D);

    float4 d = make_float4(v.x - mu, v.y - mu, v.z - mu, v.w - mu);
    float vs = d.x * d.x + d.y * d.y + d.z * d.z + d.w * d.w;
    vs = block_sum(vs, red);
    const float rstd = rsqrtf(vs * (1.0f / D) + 1e-5f);

    float4 gv = *(const float4*)(g + i);
    float4 bv = *(const float4*)(beta + i);
    float4 o = make_float4(d.x * rstd * gv.x + bv.x, d.y * rstd * gv.y + bv.y,
                           d.z * rstd * gv.z + bv.z, d.w * rstd * gv.w + bv.w);
    *(__half2*)(xr16 + i)     = __floats2half2_rn(o.x, o.y);
    *(__half2*)(xr16 + i + 2) = __floats2half2_rn(o.z, o.w);
}

// ---------------- log_softmax: fp16 logits -> fp32 out (smem row cache) ------
__global__ void log_softmax_kernel(const __half* __restrict__ logits,
                                   float* __restrict__ out) {
    extern __shared__ __half srow[];
    const __half* row = logits + (size_t)blockIdx.x * V;
    float* orow = out + (size_t)blockIdx.x * V;
    __shared__ float red[32];
    const int tid = threadIdx.x;

    float m = -INFINITY;
    for (int i = tid * 2; i < V; i += blockDim.x * 2) {
        __half2 h = *(const __half2*)(row + i);
        *(__half2*)(srow + i) = h;
        m = fmaxf(m, fmaxf(__low2float(h), __high2float(h)));
    }
    __syncthreads();
    float M = block_max(m, red);

    float s = 0.0f;
    for (int i = tid * 2; i < V; i += blockDim.x * 2) {
        __half2 h = *(const __half2*)(srow + i);
        s += expf(__low2float(h) - M) + expf(__high2float(h) - M);
    }
    float sum = block_sum(s, red);
    const float lse = M + logf(sum);

    for (int i = tid * 2; i < V; i += blockDim.x * 2) {
        __half2 h = *(const __half2*)(srow + i);
        float2 o = make_float2(__low2float(h) - lse, __high2float(h) - lse);
        *(float2*)(orow + i) = o;
    }
}

// ---------------- launch -------------------------------------------------------
extern "C" void kernel_launch(void* const* d_in, const int* in_sizes, int n_in,
                              void* d_out, int out_size) {
    const int*   tokens = (const int*)  d_in[0];
    const float* embed  = (const float*)d_in[1];
    const float* Wq     = (const float*)d_in[2];
    const float* bq     = (const float*)d_in[3];
    const float* Wk     = (const float*)d_in[4];
    const float* bk     = (const float*)d_in[5];
    const float* Wv     = (const float*)d_in[6];
    const float* bv     = (const float*)d_in[7];
    const float* g1     = (const float*)d_in[8];
    const float* beta1  = (const float*)d_in[9];
    const float* W1     = (const float*)d_in[10];
    const float* bf1    = (const float*)d_in[11];
    const float* W2     = (const float*)d_in[12];
    const float* bf2    = (const float*)d_in[13];
    const float* g2     = (const float*)d_in[14];
    const float* beta2  = (const float*)d_in[15];
    const float* Wout   = (const float*)d_in[16];
    const float* bout   = (const float*)d_in[17];
    float* out = (float*)d_out;

    __half *x16, *qkv16, *attn16, *scores16, *probs16, *h16, *logits16;
    __half *wqkv16, *w1T16, *w2T16, *wout16;
    cudaGetSymbolAddress((void**)&x16,      g_x16);
    cudaGetSymbolAddress((void**)&qkv16,    g_qkv16);
    cudaGetSymbolAddress((void**)&attn16,   g_attn16);
    cudaGetSymbolAddress((void**)&scores16, g_scores16);
    cudaGetSymbolAddress((void**)&probs16,  g_probs16);
    cudaGetSymbolAddress((void**)&h16,      g_h16);
    cudaGetSymbolAddress((void**)&logits16, g_logits16);
    cudaGetSymbolAddress((void**)&wqkv16,   g_wqkv16);
    cudaGetSymbolAddress((void**)&w1T16,    g_w1T16);
    cudaGetSymbolAddress((void**)&w2T16,    g_w2T16);
    cudaGetSymbolAddress((void**)&wout16,   g_wout16);
    __half* q16 = qkv16;
    __half* k16 = qkv16 + (size_t)BT * D;
    __half* v16 = qkv16 + (size_t)2 * BT * D;

    cudaFuncSetAttribute(gemm16<0, false, true,  true,  0, 0>, cudaFuncAttributeMaxDynamicSharedMemorySize, GEMM_SMEM16);
    cudaFuncSetAttribute(gemm16<0, true,  true,  true,  0, 0>, cudaFuncAttributeMaxDynamicSharedMemorySize, GEMM_SMEM16);
    cudaFuncSetAttribute(gemm16<0, false, true,  true,  0, 1>, cudaFuncAttributeMaxDynamicSharedMemorySize, GEMM_SMEM16);
    cudaFuncSetAttribute(gemm16<1, false, false, true,  0, 0>, cudaFuncAttributeMaxDynamicSharedMemorySize, GEMM_SMEM16);
    cudaFuncSetAttribute(gemm16<2, false, false, true,  1, 0>, cudaFuncAttributeMaxDynamicSharedMemorySize, GEMM_SMEM16);
    cudaFuncSetAttribute(log_softmax_kernel, cudaFuncAttributeMaxDynamicSharedMemorySize, V * 2);

    dim3 tb(32, 8);
    // launches 1-5 (6th launch, captured by ncu, is the QKV GEMM)
    transpose_f2h_kernel<<<dim3(D / 32, D / 64, L), tb>>>(Wq, wqkv16 + 0 * (size_t)D * D, D, D, (long)D * D, (long)3 * D * D);
    transpose_f2h_kernel<<<dim3(D / 32, D / 64, L), tb>>>(Wk, wqkv16 + 1 * (size_t)D * D, D, D, (long)D * D, (long)3 * D * D);
    transpose_f2h_kernel<<<dim3(DF / 32, D / 64, L), tb>>>(W1, w1T16, D, DF, (long)D * DF, (long)DF * D);
    transpose_f2h_kernel<<<dim3(D / 32, DF / 64, L), tb>>>(W2, w2T16, DF, D, (long)DF * D, (long)D * DF);
    embed_pe_kernel<<<BT, 256>>>(tokens, embed, x16);

    bool rest_transposed = false;

    for (int l = 0; l < L; ++l) {
        if (l == 0) {
            // needed before first QKV consumes Wv slice
            transpose_f2h_kernel<<<dim3(D / 32, D / 64, L), tb>>>(Wv, wqkv16 + 2 * (size_t)D * D, D, D, (long)D * D, (long)3 * D * D);
        }

        // fused QKV -> fp16 (z = 0,1,2 selects weight slice + bias + out slice)
        gemm16<0, false, true, true, 0, 0><<<dim3(D / 128, BT / 128, 3), 256, GEMM_SMEM16>>>(
            x16, wqkv16 + (size_t)l * 3 * D * D,
            bq + (size_t)l * D, bk + (size_t)l * D, bv + (size_t)l * D,
            qkv16, D, D, 0, (long)D * D, (long)BT * D, 1.0f);

        if (!rest_transposed) {
            // Wout: in [R=D, C=V] -> grid (C/32, R/64)
            transpose_f2h_kernel<<<dim3(V / 32, D / 64, 1), tb>>>(Wout, wout16, D, V, 0, 0);
            rest_transposed = true;
        }

        // scores = (q @ k^T) / sqrt(D) -> fp16 (causal tile skip)
        gemm16<1, false, false, true, 0, 0><<<dim3(T / 128, T / 128, B), 256, GEMM_SMEM16>>>(
            q16, k16, nullptr, nullptr, nullptr,
            scores16, T, D, (long)T * D, (long)T * D, (long)T * T, 0.03125f);

        softmax_causal_kernel<<<dim3(T, B, 1), 256>>>(scores16, probs16);

        // attn = probs @ V -> fp16 (NN-B via trans ldmatrix; K truncated at bm+128)
        gemm16<2, false, false, true, 1, 0><<<dim3(D / 128, T / 128, B), 256, GEMM_SMEM16>>>(
            probs16, v16, nullptr, nullptr, nullptr,
            attn16, D, T, (long)T * T, (long)T * D, (long)T * D, 1.0f);

        add_ln_kernel<<<BT, 256>>>(x16, attn16, g1 + (size_t)l * D, beta1 + (size_t)l * D);

        // FFN1 -> fp16 h (relu)
        gemm16<0, true, true, true, 0, 0><<<dim3(DF / 128, BT / 128, 1), 256, GEMM_SMEM16>>>(
            x16, w1T16 + (size_t)l * DF * D,
            bf1 + (size_t)l * DF, nullptr, nullptr,
            h16, DF, D, 0, 0, 0, 1.0f);
        // FFN2 -> fp16 attn
        gemm16<0, false, true, true, 0, 0><<<dim3(D / 128, BT / 128, 1), 256, GEMM_SMEM16>>>(
            h16, w2T16 + (size_t)l * D * DF,
            bf2 + (size_t)l * D, nullptr, nullptr,
            attn16, D, DF, 0, 0, 0, 1.0f);

        add_ln_kernel<<<BT, 256>>>(x16, attn16, g2 + (size_t)l * D, beta2 + (size_t)l * D);
    }

    // vocab projection -> fp16 logits (SWAP grid), then log_softmax -> fp32 out
    gemm16<0, false, true, true, 0, 1><<<dim3(BT / 128, V / 128, 1), 256, GEMM_SMEM16>>>(
        x16, wout16, bout, nullptr, nullptr,
        logits16, V, D, 0, 0, 0, 1.0f);
    log_softmax_kernel<<<BT, 512, V * 2>>>(logits16, out);
}